// round 1
// baseline (speedup 1.0000x reference)
#include <cuda_runtime.h>

#define SIZE  256
#define PREV  256
#define BATCH 32768

#define BM 128
#define BN 64
#define BK 32

// ---------------- scratch (no allocation allowed) ----------------
__device__ float g_pa[SIZE * PREV];
__device__ float g_pb[SIZE * PREV];
__device__ float g_c0[SIZE];
__device__ float g_cA[SIZE];
__device__ float g_cB[SIZE];
__device__ float g_cAB[SIZE];

// ---------------- prep kernel 1: row softmax of wa and wb ----------------
// 512 blocks x 256 threads; block r < 256 handles wa row r, else wb row r-256.
__global__ void softmax_rows_kernel(const float* __restrict__ wa,
                                    const float* __restrict__ wb) {
    const int r = blockIdx.x;
    const float* src = (r < SIZE) ? (wa + r * PREV) : (wb + (r - SIZE) * PREV);
    float* dst       = (r < SIZE) ? (g_pa + r * PREV) : (g_pb + (r - SIZE) * PREV);

    const int t = threadIdx.x;  // 0..255, one element per thread
    float v = src[t];

    __shared__ float red[8];
    // block max
    float m = v;
    #pragma unroll
    for (int o = 16; o; o >>= 1) m = fmaxf(m, __shfl_xor_sync(0xffffffffu, m, o));
    if ((t & 31) == 0) red[t >> 5] = m;
    __syncthreads();
    if (t < 8) {
        float mm = red[t];
        #pragma unroll
        for (int o = 4; o; o >>= 1) mm = fmaxf(mm, __shfl_xor_sync(0xffu, mm, o));
        if (t == 0) red[0] = mm;
    }
    __syncthreads();
    m = red[0];
    __syncthreads();

    float e = expf(v - m);
    // block sum
    float s = e;
    #pragma unroll
    for (int o = 16; o; o >>= 1) s += __shfl_xor_sync(0xffffffffu, s, o);
    if ((t & 31) == 0) red[t >> 5] = s;
    __syncthreads();
    if (t < 8) {
        float ss = red[t];
        #pragma unroll
        for (int o = 4; o; o >>= 1) ss += __shfl_xor_sync(0xffu, ss, o);
        if (t == 0) red[0] = ss;
    }
    __syncthreads();

    dst[t] = e / red[0];
}

// ---------------- prep kernel 2: gate-table coefficients ----------------
// out[j,b] = c0 + cA*A + cB*B + cAB*A*B  (each gate is affine in {1,A,B,AB})
__global__ void coef_kernel(const float* __restrict__ wt) {
    const int j = threadIdx.x;  // 0..255
    float p[16];
    float m = -1e30f;
    #pragma unroll
    for (int g = 0; g < 16; g++) {
        p[g] = wt[g * SIZE + j];  // wt is [16, SIZE] row-major
        m = fmaxf(m, p[g]);
    }
    float s = 0.f;
    #pragma unroll
    for (int g = 0; g < 16; g++) { p[g] = expf(p[g] - m); s += p[g]; }
    const float inv = 1.0f / s;
    #pragma unroll
    for (int g = 0; g < 16; g++) p[g] *= inv;

    g_c0[j]  = p[8] + p[9] + p[10] + p[11] + p[12] + p[13] + p[14] + p[15];
    g_cA[j]  = p[2] + p[3] + p[6] + p[7] - p[8] - p[9] - p[12] - p[13];
    g_cB[j]  = p[4] + p[5] + p[6] + p[7] - p[8] - p[9] - p[10] - p[11];
    g_cAB[j] = p[1] - p[2] - p[4] - 2.f * p[6] - p[7]
             + p[8] + 2.f * p[9] + p[11] + p[13] - p[14];
}

// ---------------- main fused kernel ----------------
// Block computes out tile [BM x BN]. Both GEMMs (A via pa, B via pb) share the
// same x tile in smem. 256 threads: tm = tid>>3 (0..31) -> 4 rows each,
// tn = tid&7 (0..7) -> 8 cols each. Epilogue applies the closed-form gate mix.
__global__ __launch_bounds__(256, 2)
void fused_logic_gemm_kernel(const float* __restrict__ x,
                             float* __restrict__ out) {
    __shared__ float sA[BK][BM + 4];   // pa tile, k-major (+4 pad, keeps 16B align)
    __shared__ float sB[BK][BM + 4];   // pb tile, k-major
    __shared__ float sX[BK][BN];       // x tile

    const int tid = threadIdx.x;
    const int tm  = tid >> 3;   // 0..31 -> rows tm*4 .. tm*4+3
    const int tn  = tid & 7;    // 0..7  -> cols tn*8 .. tn*8+7
    const int m0  = blockIdx.y * BM;
    const int n0  = blockIdx.x * BN;

    float accA[4][8];
    float accB[4][8];
    #pragma unroll
    for (int r = 0; r < 4; r++)
        #pragma unroll
        for (int c = 0; c < 8; c++) { accA[r][c] = 0.f; accB[r][c] = 0.f; }

    for (int kt = 0; kt < PREV; kt += BK) {
        // load pa/pb tiles: 128 rows x 32 k, transposed into k-major smem
        #pragma unroll
        for (int i = 0; i < 4; i++) {
            const int f   = tid + i * 256;       // 0..1023
            const int row = f >> 3;              // 0..127
            const int kq  = (f & 7) * 4;         // 0,4,..,28
            const float4 va = *(const float4*)&g_pa[(m0 + row) * PREV + kt + kq];
            const float4 vb = *(const float4*)&g_pb[(m0 + row) * PREV + kt + kq];
            sA[kq + 0][row] = va.x; sA[kq + 1][row] = va.y;
            sA[kq + 2][row] = va.z; sA[kq + 3][row] = va.w;
            sB[kq + 0][row] = vb.x; sB[kq + 1][row] = vb.y;
            sB[kq + 2][row] = vb.z; sB[kq + 3][row] = vb.w;
        }
        // load x tile: 32 k-rows x 64 cols
        #pragma unroll
        for (int i = 0; i < 2; i++) {
            const int f  = tid + i * 256;        // 0..511
            const int kr = f >> 4;               // 0..31
            const int nq = (f & 15) * 4;         // 0,4,..,60
            *(float4*)&sX[kr][nq] =
                *(const float4*)&x[(size_t)(kt + kr) * BATCH + n0 + nq];
        }
        __syncthreads();

        #pragma unroll
        for (int k = 0; k < BK; k++) {
            const float4 a  = *(const float4*)&sA[k][tm * 4];
            const float4 b  = *(const float4*)&sB[k][tm * 4];
            const float4 x0 = *(const float4*)&sX[k][tn * 8];
            const float4 x1 = *(const float4*)&sX[k][tn * 8 + 4];
            const float ar[4] = {a.x, a.y, a.z, a.w};
            const float br[4] = {b.x, b.y, b.z, b.w};
            const float xr[8] = {x0.x, x0.y, x0.z, x0.w, x1.x, x1.y, x1.z, x1.w};
            #pragma unroll
            for (int r = 0; r < 4; r++)
                #pragma unroll
                for (int c = 0; c < 8; c++) {
                    accA[r][c] = fmaf(ar[r], xr[c], accA[r][c]);
                    accB[r][c] = fmaf(br[r], xr[c], accB[r][c]);
                }
        }
        __syncthreads();
    }

    // epilogue: out = c0 + cA*A + cB*B + cAB*A*B, coalesced 2x float4 per row
    #pragma unroll
    for (int r = 0; r < 4; r++) {
        const int j   = m0 + tm * 4 + r;
        const float c0  = g_c0[j];
        const float cA  = g_cA[j];
        const float cB  = g_cB[j];
        const float cAB = g_cAB[j];
        float o[8];
        #pragma unroll
        for (int c = 0; c < 8; c++) {
            const float A = accA[r][c];
            const float B = accB[r][c];
            o[c] = fmaf(cAB * A, B, fmaf(cA, A, fmaf(cB, B, c0)));
        }
        float* dst = &out[(size_t)j * BATCH + n0 + tn * 8];
        *(float4*)(dst)     = make_float4(o[0], o[1], o[2], o[3]);
        *(float4*)(dst + 4) = make_float4(o[4], o[5], o[6], o[7]);
    }
}

// ---------------- launch ----------------
extern "C" void kernel_launch(void* const* d_in, const int* in_sizes, int n_in,
                              void* d_out, int out_size) {
    const float* x  = (const float*)d_in[0];   // [PREV,  BATCH]
    const float* wa = (const float*)d_in[1];   // [SIZE,  PREV]
    const float* wb = (const float*)d_in[2];   // [SIZE,  PREV]
    const float* wt = (const float*)d_in[3];   // [16,    SIZE]
    float* out = (float*)d_out;                // [SIZE,  BATCH]

    softmax_rows_kernel<<<2 * SIZE, 256>>>(wa, wb);
    coef_kernel<<<1, 256>>>(wt);

    dim3 grid(BATCH / BN, SIZE / BM);  // (512, 2)
    fused_logic_gemm_kernel<<<grid, 256>>>(x, out);
}

// round 3
// speedup vs baseline: 1.9829x; 1.9829x over previous
#include <cuda_runtime.h>
#include <cuda_bf16.h>
#include <cstdint>

#define SIZE  256
#define PREV  256
#define BATCH 32768

#define BM 128
#define BN 128
#define BK 32
#define NUM_KTILES (PREV / BK)   // 8

// ---------------- scratch (no allocation allowed) ----------------
__device__ __align__(128) __nv_bfloat16 g_wah[SIZE * PREV];
__device__ __align__(128) __nv_bfloat16 g_wal[SIZE * PREV];
__device__ __align__(128) __nv_bfloat16 g_wbh[SIZE * PREV];
__device__ __align__(128) __nv_bfloat16 g_wbl[SIZE * PREV];
__device__ __align__(128) __nv_bfloat16 g_xh[PREV * BATCH];  // x hi, same [K][N] layout
__device__ __align__(128) __nv_bfloat16 g_xl[PREV * BATCH];  // x lo
__device__ float g_c0[SIZE];
__device__ float g_cA[SIZE];
__device__ float g_cB[SIZE];
__device__ float g_cAB[SIZE];

// ---------------- smem layout (bytes) ----------------
// W tiles: 128 rows x 32k bf16 = 64B/row, padded to 80B  -> 10240 B each
// X tiles: 32 rows x 128n bf16 = 256B/row, padded to 272B -> 8704 B each
#define WPAD 80
#define XPAD 272
#define W_TILE_BYTES (128 * WPAD)          // 10240
#define X_TILE_BYTES (32 * XPAD)           // 8704
#define OFF_WAH 0
#define OFF_WAL (OFF_WAH + W_TILE_BYTES)
#define OFF_WBH (OFF_WAL + W_TILE_BYTES)
#define OFF_WBL (OFF_WBH + W_TILE_BYTES)
#define OFF_XH  (OFF_WBL + W_TILE_BYTES)   // 40960
#define OFF_XL  (OFF_XH + X_TILE_BYTES)    // 49664
#define STAGE   (OFF_XL + X_TILE_BYTES)    // 58368
#define SMEM_TOTAL (2 * STAGE)             // 116736

// ============================ PTX helpers ============================
__device__ __forceinline__ uint32_t smem_u32(const void* p) {
    uint32_t a;
    asm("{ .reg .u64 t; cvta.to.shared.u64 t, %1; cvt.u32.u64 %0, t; }" : "=r"(a) : "l"(p));
    return a;
}
#define CP_ASYNC16(dst, src) \
    asm volatile("cp.async.cg.shared.global [%0], [%1], 16;" :: "r"(dst), "l"(src))
#define CP_COMMIT() asm volatile("cp.async.commit_group;" ::: "memory")
#define CP_WAIT(n)  asm volatile("cp.async.wait_group %0;" :: "n"(n) : "memory")

#define LDSM_X4(r0, r1, r2, r3, addr)                                           \
    asm volatile("ldmatrix.sync.aligned.m8n8.x4.shared.b16 {%0,%1,%2,%3}, [%4];" \
                 : "=r"(r0), "=r"(r1), "=r"(r2), "=r"(r3) : "r"(addr))
#define LDSM_X4_T(r0, r1, r2, r3, addr)                                         \
    asm volatile("ldmatrix.sync.aligned.m8n8.x4.trans.shared.b16 {%0,%1,%2,%3}, [%4];" \
                 : "=r"(r0), "=r"(r1), "=r"(r2), "=r"(r3) : "r"(addr))

#define MMA_BF16(c, a, b)                                                       \
    asm volatile("mma.sync.aligned.m16n8k16.row.col.f32.bf16.bf16.f32 "         \
                 "{%0,%1,%2,%3}, {%4,%5,%6,%7}, {%8,%9}, {%0,%1,%2,%3};"        \
                 : "+f"((c)[0]), "+f"((c)[1]), "+f"((c)[2]), "+f"((c)[3])       \
                 : "r"((a)[0]), "r"((a)[1]), "r"((a)[2]), "r"((a)[3]),          \
                   "r"((b)[0]), "r"((b)[1]))

// ---------------- prep 1: row softmax of wa/wb -> bf16 hi/lo ----------------
__global__ void softmax_rows_kernel(const float* __restrict__ wa,
                                    const float* __restrict__ wb) {
    const int r = blockIdx.x;
    const float* src = (r < SIZE) ? (wa + r * PREV) : (wb + (r - SIZE) * PREV);
    __nv_bfloat16* dh = (r < SIZE) ? (g_wah + r * PREV) : (g_wbh + (r - SIZE) * PREV);
    __nv_bfloat16* dl = (r < SIZE) ? (g_wal + r * PREV) : (g_wbl + (r - SIZE) * PREV);

    const int t = threadIdx.x;
    float v = src[t];
    __shared__ float red[8];
    float m = v;
    #pragma unroll
    for (int o = 16; o; o >>= 1) m = fmaxf(m, __shfl_xor_sync(0xffffffffu, m, o));
    if ((t & 31) == 0) red[t >> 5] = m;
    __syncthreads();
    if (t < 8) {
        float mm = red[t];
        #pragma unroll
        for (int o = 4; o; o >>= 1) mm = fmaxf(mm, __shfl_xor_sync(0xffu, mm, o));
        if (t == 0) red[0] = mm;
    }
    __syncthreads();
    m = red[0];
    __syncthreads();
    float e = expf(v - m);
    float s = e;
    #pragma unroll
    for (int o = 16; o; o >>= 1) s += __shfl_xor_sync(0xffffffffu, s, o);
    if ((t & 31) == 0) red[t >> 5] = s;
    __syncthreads();
    if (t < 8) {
        float ss = red[t];
        #pragma unroll
        for (int o = 4; o; o >>= 1) ss += __shfl_xor_sync(0xffu, ss, o);
        if (t == 0) red[0] = ss;
    }
    __syncthreads();
    float p = e / red[0];
    __nv_bfloat16 hi = __float2bfloat16(p);
    dh[t] = hi;
    dl[t] = __float2bfloat16(p - __bfloat162float(hi));
}

// ---------------- prep 2: gate-table coefficients ----------------
__global__ void coef_kernel(const float* __restrict__ wt) {
    const int j = threadIdx.x;
    float p[16];
    float m = -1e30f;
    #pragma unroll
    for (int g = 0; g < 16; g++) { p[g] = wt[g * SIZE + j]; m = fmaxf(m, p[g]); }
    float s = 0.f;
    #pragma unroll
    for (int g = 0; g < 16; g++) { p[g] = expf(p[g] - m); s += p[g]; }
    const float inv = 1.0f / s;
    #pragma unroll
    for (int g = 0; g < 16; g++) p[g] *= inv;
    g_c0[j]  = p[8] + p[9] + p[10] + p[11] + p[12] + p[13] + p[14] + p[15];
    g_cA[j]  = p[2] + p[3] + p[6] + p[7] - p[8] - p[9] - p[12] - p[13];
    g_cB[j]  = p[4] + p[5] + p[6] + p[7] - p[8] - p[9] - p[10] - p[11];
    g_cAB[j] = p[1] - p[2] - p[4] - 2.f * p[6] - p[7]
             + p[8] + 2.f * p[9] + p[11] + p[13] - p[14];
}

// ---------------- prep 3: bf16 hi/lo split of x (same layout, no transpose) ----------------
__global__ void split_x_kernel(const float* __restrict__ x) {
    const size_t i = ((size_t)blockIdx.x * 256 + threadIdx.x) * 4;
    const float4 v = *(const float4*)(x + i);
    __nv_bfloat16 h0 = __float2bfloat16(v.x), h1 = __float2bfloat16(v.y);
    __nv_bfloat16 h2 = __float2bfloat16(v.z), h3 = __float2bfloat16(v.w);
    __nv_bfloat16 l0 = __float2bfloat16(v.x - __bfloat162float(h0));
    __nv_bfloat16 l1 = __float2bfloat16(v.y - __bfloat162float(h1));
    __nv_bfloat16 l2 = __float2bfloat16(v.z - __bfloat162float(h2));
    __nv_bfloat16 l3 = __float2bfloat16(v.w - __bfloat162float(h3));
    ushort4 hh, ll;
    hh.x = *(unsigned short*)&h0; hh.y = *(unsigned short*)&h1;
    hh.z = *(unsigned short*)&h2; hh.w = *(unsigned short*)&h3;
    ll.x = *(unsigned short*)&l0; ll.y = *(unsigned short*)&l1;
    ll.z = *(unsigned short*)&l2; ll.w = *(unsigned short*)&l3;
    *(ushort4*)(g_xh + i) = hh;
    *(ushort4*)(g_xl + i) = ll;
}

// ---------------- main fused mma.sync kernel ----------------
// CTA: out tile [128 x 128]. 8 warps as 4(m) x 2(n): each warp 32 rows x 64 cols.
// K loop: 8 tiles of BK=32; per k16 step, 3 split terms x 2 projections share X frags.
__global__ void __launch_bounds__(256, 1)
fused_logic_mma_kernel(float* __restrict__ out) {
    extern __shared__ char smem[];
    const uint32_t sb = smem_u32(smem);
    const int tid = threadIdx.x;
    const int wid = tid >> 5;
    const int lane = tid & 31;
    const int warp_m = wid >> 1;      // 0..3
    const int warp_n = wid & 1;       // 0..1
    const int m0 = blockIdx.y * BM;
    const int n0 = blockIdx.x * BN;

    float accA[2][8][4];
    float accB[2][8][4];
    #pragma unroll
    for (int mt = 0; mt < 2; mt++)
        #pragma unroll
        for (int nt = 0; nt < 8; nt++)
            #pragma unroll
            for (int e = 0; e < 4; e++) { accA[mt][nt][e] = 0.f; accB[mt][nt][e] = 0.f; }

    const __nv_bfloat16* wsrc[4] = {
        g_wah + (size_t)m0 * PREV, g_wal + (size_t)m0 * PREV,
        g_wbh + (size_t)m0 * PREV, g_wbl + (size_t)m0 * PREV };
    const uint32_t woff[4] = { OFF_WAH, OFF_WAL, OFF_WBH, OFF_WBL };

    // ---- cp.async issue of one k-tile into stage kt&1 ----
    auto issue = [&](int kt) {
        const uint32_t base = sb + (kt & 1) * STAGE;
        // W: 4 variants x 128 rows x 4 chunks(16B) = 2048 chunks
        #pragma unroll
        for (int i = 0; i < 8; i++) {
            int flat = tid + i * 256;
            int v = flat >> 9, rem = flat & 511, m = rem >> 2, c = rem & 3;
            const char* src = (const char*)(wsrc[v] + (size_t)m * PREV + kt * BK + c * 8);
            CP_ASYNC16(base + woff[v] + m * WPAD + c * 16, src);
        }
        // X: 2 variants x 32 rows x 16 chunks = 1024 chunks
        #pragma unroll
        for (int i = 0; i < 4; i++) {
            int flat = tid + i * 256;
            int h = flat >> 9, rem = flat & 511, k = rem >> 4, c = rem & 15;
            const __nv_bfloat16* xa = h ? g_xl : g_xh;
            const char* src = (const char*)(xa + (size_t)(kt * BK + k) * BATCH + n0 + c * 8);
            CP_ASYNC16(base + (h ? OFF_XL : OFF_XH) + k * XPAD + c * 16, src);
        }
        CP_COMMIT();
    };

    // ldmatrix per-lane address components
    const int g8 = lane >> 3;                       // matrix group 0..3
    const int r8 = lane & 7;                        // row within group
    const int a_row = (g8 & 1) * 8 + r8;            // W tile row within m16
    const uint32_t a_base_off = a_row * WPAD + (g8 >> 1) * 16 + warp_m * 32 * WPAD;
    const uint32_t x_base_off = ((g8 & 1) * 8 + r8) * XPAD + (g8 >> 1) * 16 + warp_n * 128;

    issue(0);
    for (int kt = 0; kt < NUM_KTILES; kt++) {
        if (kt + 1 < NUM_KTILES) { issue(kt + 1); CP_WAIT(1); }
        else                     { CP_WAIT(0); }
        __syncthreads();

        const uint32_t base = sb + (kt & 1) * STAGE;
        #pragma unroll
        for (int ks = 0; ks < 2; ks++) {
            // ---- W fragments: 4 variants x 2 m-tiles ----
            uint32_t fah[2][4], fal[2][4], fbh[2][4], fbl[2][4];
            #pragma unroll
            for (int mt = 0; mt < 2; mt++) {
                const uint32_t ao = base + a_base_off + mt * 16 * WPAD + ks * 32;
                LDSM_X4(fah[mt][0], fah[mt][1], fah[mt][2], fah[mt][3], ao + OFF_WAH);
                LDSM_X4(fal[mt][0], fal[mt][1], fal[mt][2], fal[mt][3], ao + OFF_WAL);
                LDSM_X4(fbh[mt][0], fbh[mt][1], fbh[mt][2], fbh[mt][3], ao + OFF_WBH);
                LDSM_X4(fbl[mt][0], fbl[mt][1], fbl[mt][2], fbl[mt][3], ao + OFF_WBL);
            }
            // ---- X fragments: 8 n-tiles x hi/lo (shared by both projections) ----
            uint32_t xh[8][2], xl[8][2];
            #pragma unroll
            for (int j = 0; j < 4; j++) {
                const uint32_t xo = base + x_base_off + ks * 16 * XPAD + j * 32;
                uint32_t r0, r1, r2, r3;
                LDSM_X4_T(r0, r1, r2, r3, xo + OFF_XH);
                xh[2 * j][0] = r0; xh[2 * j][1] = r1;
                xh[2 * j + 1][0] = r2; xh[2 * j + 1][1] = r3;
                LDSM_X4_T(r0, r1, r2, r3, xo + OFF_XL);
                xl[2 * j][0] = r0; xl[2 * j][1] = r1;
                xl[2 * j + 1][0] = r2; xl[2 * j + 1][1] = r3;
            }
            // ---- 96 MMAs: 3 terms x 2 projections x 2 m-tiles x 8 n-tiles ----
            #pragma unroll
            for (int mt = 0; mt < 2; mt++)
                #pragma unroll
                for (int nt = 0; nt < 8; nt++) {
                    MMA_BF16(accA[mt][nt], fah[mt], xh[nt]);
                    MMA_BF16(accA[mt][nt], fah[mt], xl[nt]);
                    MMA_BF16(accA[mt][nt], fal[mt], xh[nt]);
                    MMA_BF16(accB[mt][nt], fbh[mt], xh[nt]);
                    MMA_BF16(accB[mt][nt], fbh[mt], xl[nt]);
                    MMA_BF16(accB[mt][nt], fbl[mt], xh[nt]);
                }
        }
        __syncthreads();
    }

    // ---- epilogue: out = c0 + cA*A + cB*B + cAB*A*B ----
    #pragma unroll
    for (int mt = 0; mt < 2; mt++) {
        const int j1 = m0 + warp_m * 32 + mt * 16 + (lane >> 2);
        const int j2 = j1 + 8;
        const float c0a = g_c0[j1], cAa = g_cA[j1], cBa = g_cB[j1], cXa = g_cAB[j1];
        const float c0b = g_c0[j2], cAb = g_cA[j2], cBb = g_cB[j2], cXb = g_cAB[j2];
        #pragma unroll
        for (int nt = 0; nt < 8; nt++) {
            const int n = n0 + warp_n * 64 + nt * 8 + (lane & 3) * 2;
            float2 o1, o2;
            {
                float A = accA[mt][nt][0], B = accB[mt][nt][0];
                o1.x = fmaf(cXa * A, B, fmaf(cAa, A, fmaf(cBa, B, c0a)));
                A = accA[mt][nt][1]; B = accB[mt][nt][1];
                o1.y = fmaf(cXa * A, B, fmaf(cAa, A, fmaf(cBa, B, c0a)));
            }
            {
                float A = accA[mt][nt][2], B = accB[mt][nt][2];
                o2.x = fmaf(cXb * A, B, fmaf(cAb, A, fmaf(cBb, B, c0b)));
                A = accA[mt][nt][3]; B = accB[mt][nt][3];
                o2.y = fmaf(cXb * A, B, fmaf(cAb, A, fmaf(cBb, B, c0b)));
            }
            *(float2*)&out[(size_t)j1 * BATCH + n] = o1;
            *(float2*)&out[(size_t)j2 * BATCH + n] = o2;
        }
    }
}

// ---------------- launch ----------------
extern "C" void kernel_launch(void* const* d_in, const int* in_sizes, int n_in,
                              void* d_out, int out_size) {
    const float* x  = (const float*)d_in[0];   // [PREV,  BATCH]
    const float* wa = (const float*)d_in[1];   // [SIZE,  PREV]
    const float* wb = (const float*)d_in[2];   // [SIZE,  PREV]
    const float* wt = (const float*)d_in[3];   // [16,    SIZE]
    float* out = (float*)d_out;                // [SIZE,  BATCH]

    cudaFuncSetAttribute(fused_logic_mma_kernel,
                         cudaFuncAttributeMaxDynamicSharedMemorySize, SMEM_TOTAL);

    softmax_rows_kernel<<<2 * SIZE, 256>>>(wa, wb);
    coef_kernel<<<1, 256>>>(wt);
    split_x_kernel<<<(PREV * BATCH) / (256 * 4), 256>>>(x);

    dim3 grid(BATCH / BN, SIZE / BM);  // (256, 2)
    fused_logic_mma_kernel<<<grid, 256, SMEM_TOTAL>>>(out);
}

// round 5
// speedup vs baseline: 2.3453x; 1.1828x over previous
#include <cuda_runtime.h>
#include <cuda_bf16.h>
#include <cstdint>

#define SIZE  256
#define PREV  256
#define BATCH 32768

#define BM 128
#define BN 64
#define BK 32
#define NUM_KTILES (PREV / BK)   // 8

// ---------------- scratch ----------------
// W arrays stored TRANSPOSED (k-major): g_w*[k][m]  (k = PREV dim, m = SIZE dim)
__device__ __align__(128) __nv_bfloat16 g_wah[PREV * SIZE];
__device__ __align__(128) __nv_bfloat16 g_wal[PREV * SIZE];
__device__ __align__(128) __nv_bfloat16 g_wbh[PREV * SIZE];
__device__ __align__(128) __nv_bfloat16 g_wbl[PREV * SIZE];
__device__ float g_c0[SIZE];
__device__ float g_cA[SIZE];
__device__ float g_cB[SIZE];
__device__ float g_cAB[SIZE];

// ---------------- smem layout (bytes, per stage) ----------------
// W tiles (k-major): 32 k-rows x 128 m-cols x 2B = 256B/row, pad 272 -> 8704 each
// X bf16 tiles:      32 k-rows x 64 n x 2B = 128B/row, pad 144 -> 4608 each
// X f32 staging:     32 k-rows x 64 n x 4B = 256B/row, pad 272 -> 8704
#define WKPAD 272
#define XBPAD 144
#define XFPAD 272
#define OFF_WAH 0
#define OFF_WAL 8704
#define OFF_WBH 17408
#define OFF_WBL 26112
#define OFF_XH  34816
#define OFF_XL  39424
#define OFF_XF  44032
#define STAGE_SZ 52736
#define SMEM_TOTAL (2 * STAGE_SZ)   // 105472

// ============================ PTX helpers ============================
__device__ __forceinline__ uint32_t smem_u32(const void* p) {
    uint32_t a;
    asm("{ .reg .u64 t; cvta.to.shared.u64 t, %1; cvt.u32.u64 %0, t; }" : "=r"(a) : "l"(p));
    return a;
}
#define CP_ASYNC16(dst, src) \
    asm volatile("cp.async.cg.shared.global [%0], [%1], 16;" :: "r"(dst), "l"(src))
#define CP_COMMIT() asm volatile("cp.async.commit_group;" ::: "memory")
#define CP_WAIT0()  asm volatile("cp.async.wait_group 0;" ::: "memory")

#define LDSM_X4_T(r0, r1, r2, r3, addr)                                         \
    asm volatile("ldmatrix.sync.aligned.m8n8.x4.trans.shared.b16 {%0,%1,%2,%3}, [%4];" \
                 : "=r"(r0), "=r"(r1), "=r"(r2), "=r"(r3) : "r"(addr))

#define MMA_BF16(c, a, b)                                                       \
    asm volatile("mma.sync.aligned.m16n8k16.row.col.f32.bf16.bf16.f32 "         \
                 "{%0,%1,%2,%3}, {%4,%5,%6,%7}, {%8,%9}, {%0,%1,%2,%3};"        \
                 : "+f"((c)[0]), "+f"((c)[1]), "+f"((c)[2]), "+f"((c)[3])       \
                 : "r"((a)[0]), "r"((a)[1]), "r"((a)[2]), "r"((a)[3]),          \
                   "r"((b)[0]), "r"((b)[1]))

// ---------------- prep 1: row softmax of wa/wb -> TRANSPOSED bf16 hi/lo ----------------
__global__ void softmax_rows_kernel(const float* __restrict__ wa,
                                    const float* __restrict__ wb) {
    const int r = blockIdx.x;
    const float* src = (r < SIZE) ? (wa + r * PREV) : (wb + (r - SIZE) * PREV);
    __nv_bfloat16* dh = (r < SIZE) ? g_wah : g_wbh;
    __nv_bfloat16* dl = (r < SIZE) ? g_wal : g_wbl;
    const int m = (r < SIZE) ? r : (r - SIZE);

    const int t = threadIdx.x;  // k index
    float v = src[t];
    __shared__ float red[8];
    float mx = v;
    #pragma unroll
    for (int o = 16; o; o >>= 1) mx = fmaxf(mx, __shfl_xor_sync(0xffffffffu, mx, o));
    if ((t & 31) == 0) red[t >> 5] = mx;
    __syncthreads();
    if (t < 8) {
        float mm = red[t];
        #pragma unroll
        for (int o = 4; o; o >>= 1) mm = fmaxf(mm, __shfl_xor_sync(0xffu, mm, o));
        if (t == 0) red[0] = mm;
    }
    __syncthreads();
    mx = red[0];
    __syncthreads();
    float e = expf(v - mx);
    float s = e;
    #pragma unroll
    for (int o = 16; o; o >>= 1) s += __shfl_xor_sync(0xffffffffu, s, o);
    if ((t & 31) == 0) red[t >> 5] = s;
    __syncthreads();
    if (t < 8) {
        float ss = red[t];
        #pragma unroll
        for (int o = 4; o; o >>= 1) ss += __shfl_xor_sync(0xffu, ss, o);
        if (t == 0) red[0] = ss;
    }
    __syncthreads();
    float p = e / red[0];
    __nv_bfloat16 hi = __float2bfloat16(p);
    dh[t * SIZE + m] = hi;                                      // transposed [k][m]
    dl[t * SIZE + m] = __float2bfloat16(p - __bfloat162float(hi));
}

// ---------------- prep 2: gate-table coefficients ----------------
__global__ void coef_kernel(const float* __restrict__ wt) {
    const int j = threadIdx.x;
    float p[16];
    float m = -1e30f;
    #pragma unroll
    for (int g = 0; g < 16; g++) { p[g] = wt[g * SIZE + j]; m = fmaxf(m, p[g]); }
    float s = 0.f;
    #pragma unroll
    for (int g = 0; g < 16; g++) { p[g] = expf(p[g] - m); s += p[g]; }
    const float inv = 1.0f / s;
    #pragma unroll
    for (int g = 0; g < 16; g++) p[g] *= inv;
    g_c0[j]  = p[8] + p[9] + p[10] + p[11] + p[12] + p[13] + p[14] + p[15];
    g_cA[j]  = p[2] + p[3] + p[6] + p[7] - p[8] - p[9] - p[12] - p[13];
    g_cB[j]  = p[4] + p[5] + p[6] + p[7] - p[8] - p[9] - p[10] - p[11];
    g_cAB[j] = p[1] - p[2] - p[4] - 2.f * p[6] - p[7]
             + p[8] + 2.f * p[9] + p[11] + p[13] - p[14];
}

// ---------------- main fused kernel ----------------
// CTA: out tile [128 x 64]. 8 warps as 4(m) x 2(n): each warp 32x32.
// Per k-tile: cp.async W (bf16 k-major) + x (fp32) -> in-smem hi/lo split of x
// -> ldmatrix.trans for both A (W) and B (X) fragments -> 3-term bf16 MMA.
__global__ void __launch_bounds__(256, 2)
fused_logic_mma_kernel(const float* __restrict__ x, float* __restrict__ out) {
    extern __shared__ char smem[];
    const uint32_t sb = smem_u32(smem);
    const int tid = threadIdx.x;
    const int wid = tid >> 5;
    const int lane = tid & 31;
    const int warp_m = wid >> 1;      // 0..3
    const int warp_n = wid & 1;       // 0..1
    const int m0 = blockIdx.y * BM;
    const int n0 = blockIdx.x * BN;

    float accA[2][4][4];
    float accB[2][4][4];
    #pragma unroll
    for (int mt = 0; mt < 2; mt++)
        #pragma unroll
        for (int nt = 0; nt < 4; nt++)
            #pragma unroll
            for (int e = 0; e < 4; e++) { accA[mt][nt][e] = 0.f; accB[mt][nt][e] = 0.f; }

    const __nv_bfloat16* wsrc[4] = { g_wah, g_wal, g_wbh, g_wbl };

    // ---- cp.async issue of one k-tile into stage kt&1 ----
    auto issue = [&](int kt) {
        const uint32_t base = sb + (kt & 1) * STAGE_SZ;
        // W: 4 variants x 32 k-rows x 16 chunks(16B over 128 m) = 2048 chunks
        #pragma unroll
        for (int i = 0; i < 8; i++) {
            int flat = tid + i * 256;               // 0..2047
            int v = flat >> 9, rem = flat & 511, k = rem >> 4, c = rem & 15;
            const char* src = (const char*)(wsrc[v] + (size_t)(kt * BK + k) * SIZE + m0 + c * 8);
            CP_ASYNC16(base + v * 8704 + k * WKPAD + c * 16, src);
        }
        // X fp32: 32 k-rows x 16 chunks(16B = 4 floats over 64 n) = 512 chunks
        #pragma unroll
        for (int i = 0; i < 2; i++) {
            int flat = tid + i * 256;
            int k = flat >> 4, c = flat & 15;
            const char* src = (const char*)(x + (size_t)(kt * BK + k) * BATCH + n0 + c * 4);
            CP_ASYNC16(base + OFF_XF + k * XFPAD + c * 16, src);
        }
        CP_COMMIT();
    };

    // ldmatrix per-lane address components
    const int g8 = lane >> 3;
    const int r8 = lane & 7;
    // W (A frag via trans): matrices (m-lo,k-lo),(m-hi,k-lo),(m-lo,k-hi),(m-hi,k-hi)
    const uint32_t w_off = (uint32_t)(((g8 >> 1) * 8 + r8) * WKPAD + (g8 & 1) * 16 + warp_m * 64);
    // X (B frag via trans): matrices (n-t0,k-lo),(n-t0,k-hi),(n-t1,k-lo),(n-t1,k-hi)
    const uint32_t x_off = (uint32_t)(((g8 & 1) * 8 + r8) * XBPAD + (g8 >> 1) * 16 + warp_n * 64);

    issue(0);
    for (int kt = 0; kt < NUM_KTILES; kt++) {
        const uint32_t base = sb + (kt & 1) * STAGE_SZ;
        CP_WAIT0();
        __syncthreads();

        // ---- convert x fp32 tile -> bf16 hi/lo tiles ----
        {
            const int k = tid >> 3;
            const int c8 = (tid & 7) * 8;
            const float* frow = (const float*)(smem + (kt & 1) * STAGE_SZ + OFF_XF + k * XFPAD);
            float4 v0 = *(const float4*)(frow + c8);
            float4 v1 = *(const float4*)(frow + c8 + 4);
            float vv[8] = {v0.x, v0.y, v0.z, v0.w, v1.x, v1.y, v1.z, v1.w};
            unsigned short h[8], l[8];
            #pragma unroll
            for (int e = 0; e < 8; e++) {
                __nv_bfloat16 hb = __float2bfloat16(vv[e]);
                __nv_bfloat16 lb = __float2bfloat16(vv[e] - __bfloat162float(hb));
                h[e] = *(unsigned short*)&hb;
                l[e] = *(unsigned short*)&lb;
            }
            char* hrow = smem + (kt & 1) * STAGE_SZ + OFF_XH + k * XBPAD + c8 * 2;
            char* lrow = smem + (kt & 1) * STAGE_SZ + OFF_XL + k * XBPAD + c8 * 2;
            *(ushort4*)hrow       = make_ushort4(h[0], h[1], h[2], h[3]);
            *(ushort4*)(hrow + 8) = make_ushort4(h[4], h[5], h[6], h[7]);
            *(ushort4*)lrow       = make_ushort4(l[0], l[1], l[2], l[3]);
            *(ushort4*)(lrow + 8) = make_ushort4(l[4], l[5], l[6], l[7]);
        }
        __syncthreads();

        if (kt + 1 < NUM_KTILES) issue(kt + 1);

        #pragma unroll
        for (int ks = 0; ks < 2; ks++) {
            // X fragments: 4 n-tiles x hi/lo (shared by both projections)
            uint32_t xh[4][2], xl[4][2];
            #pragma unroll
            for (int j = 0; j < 2; j++) {
                const uint32_t xo = base + x_off + ks * 16 * XBPAD + j * 32;
                uint32_t r0, r1, r2, r3;
                LDSM_X4_T(r0, r1, r2, r3, xo + OFF_XH);
                xh[2 * j][0] = r0; xh[2 * j][1] = r1;
                xh[2 * j + 1][0] = r2; xh[2 * j + 1][1] = r3;
                LDSM_X4_T(r0, r1, r2, r3, xo + OFF_XL);
                xl[2 * j][0] = r0; xl[2 * j][1] = r1;
                xl[2 * j + 1][0] = r2; xl[2 * j + 1][1] = r3;
            }
            // W fragments per mt, then 24 MMAs
            #pragma unroll
            for (int mt = 0; mt < 2; mt++) {
                const uint32_t ao = base + w_off + ks * 16 * WKPAD + mt * 32;
                uint32_t fah[4], fal[4], fbh[4], fbl[4];
                LDSM_X4_T(fah[0], fah[1], fah[2], fah[3], ao + OFF_WAH);
                LDSM_X4_T(fal[0], fal[1], fal[2], fal[3], ao + OFF_WAL);
                LDSM_X4_T(fbh[0], fbh[1], fbh[2], fbh[3], ao + OFF_WBH);
                LDSM_X4_T(fbl[0], fbl[1], fbl[2], fbl[3], ao + OFF_WBL);
                #pragma unroll
                for (int nt = 0; nt < 4; nt++) {
                    MMA_BF16(accA[mt][nt], fah, xh[nt]);
                    MMA_BF16(accA[mt][nt], fah, xl[nt]);
                    MMA_BF16(accA[mt][nt], fal, xh[nt]);
                    MMA_BF16(accB[mt][nt], fbh, xh[nt]);
                    MMA_BF16(accB[mt][nt], fbh, xl[nt]);
                    MMA_BF16(accB[mt][nt], fbl, xh[nt]);
                }
            }
        }
        __syncthreads();
    }

    // ---- epilogue: out = c0 + cA*A + cB*B + cAB*A*B ----
    const int row_in = lane >> 2;
    const int col2 = (lane & 3) * 2;
    #pragma unroll
    for (int mt = 0; mt < 2; mt++) {
        const int j1 = m0 + warp_m * 32 + mt * 16 + row_in;
        const int j2 = j1 + 8;
        const float c0a = g_c0[j1], cAa = g_cA[j1], cBa = g_cB[j1], cXa = g_cAB[j1];
        const float c0b = g_c0[j2], cAb = g_cA[j2], cBb = g_cB[j2], cXb = g_cAB[j2];
        #pragma unroll
        for (int nt = 0; nt < 4; nt++) {
            const int n = n0 + warp_n * 32 + nt * 8 + col2;
            float2 o1, o2;
            {
                float A = accA[mt][nt][0], B = accB[mt][nt][0];
                o1.x = fmaf(cXa * A, B, fmaf(cAa, A, fmaf(cBa, B, c0a)));
                A = accA[mt][nt][1]; B = accB[mt][nt][1];
                o1.y = fmaf(cXa * A, B, fmaf(cAa, A, fmaf(cBa, B, c0a)));
            }
            {
                float A = accA[mt][nt][2], B = accB[mt][nt][2];
                o2.x = fmaf(cXb * A, B, fmaf(cAb, A, fmaf(cBb, B, c0b)));
                A = accA[mt][nt][3]; B = accB[mt][nt][3];
                o2.y = fmaf(cXb * A, B, fmaf(cAb, A, fmaf(cBb, B, c0b)));
            }
            *(float2*)&out[(size_t)j1 * BATCH + n] = o1;
            *(float2*)&out[(size_t)j2 * BATCH + n] = o2;
        }
    }
}

// ---------------- launch ----------------
extern "C" void kernel_launch(void* const* d_in, const int* in_sizes, int n_in,
                              void* d_out, int out_size) {
    const float* x  = (const float*)d_in[0];   // [PREV,  BATCH]
    const float* wa = (const float*)d_in[1];   // [SIZE,  PREV]
    const float* wb = (const float*)d_in[2];   // [SIZE,  PREV]
    const float* wt = (const float*)d_in[3];   // [16,    SIZE]
    float* out = (float*)d_out;                // [SIZE,  BATCH]

    cudaFuncSetAttribute(fused_logic_mma_kernel,
                         cudaFuncAttributeMaxDynamicSharedMemorySize, SMEM_TOTAL);

    softmax_rows_kernel<<<2 * SIZE, 256>>>(wa, wb);
    coef_kernel<<<1, 256>>>(wt);

    dim3 grid(BATCH / BN, SIZE / BM);  // (512, 2)
    fused_logic_mma_kernel<<<grid, 256, SMEM_TOTAL>>>(x, out);
}

// round 6
// speedup vs baseline: 2.4513x; 1.0452x over previous
#include <cuda_runtime.h>
#include <cuda_bf16.h>
#include <cstdint>

#define SIZE  256
#define PREV  256
#define BATCH 32768

#define BM 128
#define BN 64
#define BK 32
#define NUM_KTILES (PREV / BK)   // 8

// ---------------- scratch ----------------
// W arrays stored TRANSPOSED (k-major): g_w*[k][m]
__device__ __align__(128) __nv_bfloat16 g_wah[PREV * SIZE];
__device__ __align__(128) __nv_bfloat16 g_wal[PREV * SIZE];
__device__ __align__(128) __nv_bfloat16 g_wbh[PREV * SIZE];
__device__ __align__(128) __nv_bfloat16 g_wbl[PREV * SIZE];
__device__ float g_c0[SIZE];
__device__ float g_cA[SIZE];
__device__ float g_cB[SIZE];
__device__ float g_cAB[SIZE];

// ---------------- smem layout (bytes, per stage) ----------------
// W tiles (k-major): 32 k-rows x 128 m x 2B = 256B/row, pad 272 -> 8704 each
// X bf16 tiles:      32 k-rows x 64 n x 2B = 128B/row, pad 144 -> 4608 each
#define WKPAD 272
#define XBPAD 144
#define OFF_XH  34816
#define OFF_XL  39424
#define STAGE_SZ 44032
#define SMEM_TOTAL (2 * STAGE_SZ)   // 88064

// ============================ PTX helpers ============================
__device__ __forceinline__ uint32_t smem_u32(const void* p) {
    uint32_t a;
    asm("{ .reg .u64 t; cvta.to.shared.u64 t, %1; cvt.u32.u64 %0, t; }" : "=r"(a) : "l"(p));
    return a;
}
#define CP_ASYNC16(dst, src) \
    asm volatile("cp.async.cg.shared.global [%0], [%1], 16;" :: "r"(dst), "l"(src))
#define CP_COMMIT() asm volatile("cp.async.commit_group;" ::: "memory")
#define CP_WAIT0()  asm volatile("cp.async.wait_group 0;" ::: "memory")

#define LDSM_X4_T(r0, r1, r2, r3, addr)                                         \
    asm volatile("ldmatrix.sync.aligned.m8n8.x4.trans.shared.b16 {%0,%1,%2,%3}, [%4];" \
                 : "=r"(r0), "=r"(r1), "=r"(r2), "=r"(r3) : "r"(addr))

#define MMA_BF16(c, a, b)                                                       \
    asm volatile("mma.sync.aligned.m16n8k16.row.col.f32.bf16.bf16.f32 "         \
                 "{%0,%1,%2,%3}, {%4,%5,%6,%7}, {%8,%9}, {%0,%1,%2,%3};"        \
                 : "+f"((c)[0]), "+f"((c)[1]), "+f"((c)[2]), "+f"((c)[3])       \
                 : "r"((a)[0]), "r"((a)[1]), "r"((a)[2]), "r"((a)[3]),          \
                   "r"((b)[0]), "r"((b)[1]))

// ---------------- prep 1: softmax rows -> transposed bf16 hi/lo, coalesced ----------------
// 16 blocks: block b handles 32 rows (m-block) of wa (b<8) or wb (b>=8).
// Warp reduction per row (each warp owns 4 rows), smem-staged transpose,
// 64B-coalesced global writes.
__global__ void softmax_rows_kernel(const float* __restrict__ wa,
                                    const float* __restrict__ wb) {
    __shared__ unsigned short sh[PREV * 32];   // [k][mloc] hi
    __shared__ unsigned short sl[PREV * 32];   // [k][mloc] lo
    const int bx = blockIdx.x;
    const float* src = (bx < 8) ? wa : wb;
    __nv_bfloat16* dh = (bx < 8) ? g_wah : g_wbh;
    __nv_bfloat16* dl = (bx < 8) ? g_wal : g_wbl;
    const int m0 = (bx & 7) * 32;
    const int wid = threadIdx.x >> 5;
    const int lane = threadIdx.x & 31;

    #pragma unroll
    for (int r = 0; r < 4; r++) {
        const int mloc = wid * 4 + r;
        const float* row = src + (size_t)(m0 + mloc) * PREV;
        float v[8];
        float mx = -1e30f;
        #pragma unroll
        for (int i = 0; i < 8; i++) { v[i] = row[lane + 32 * i]; mx = fmaxf(mx, v[i]); }
        #pragma unroll
        for (int o = 16; o; o >>= 1) mx = fmaxf(mx, __shfl_xor_sync(0xffffffffu, mx, o));
        float e[8], s = 0.f;
        #pragma unroll
        for (int i = 0; i < 8; i++) { e[i] = expf(v[i] - mx); s += e[i]; }
        #pragma unroll
        for (int o = 16; o; o >>= 1) s += __shfl_xor_sync(0xffffffffu, s, o);
        const float inv = 1.0f / s;
        #pragma unroll
        for (int i = 0; i < 8; i++) {
            float p = e[i] * inv;
            __nv_bfloat16 hb = __float2bfloat16(p);
            __nv_bfloat16 lb = __float2bfloat16(p - __bfloat162float(hb));
            const int k = lane + 32 * i;
            sh[k * 32 + mloc] = *(unsigned short*)&hb;
            sl[k * 32 + mloc] = *(unsigned short*)&lb;
        }
    }
    __syncthreads();
    // coalesced writes: 2048 8B chunks per array
    #pragma unroll
    for (int p = 0; p < 8; p++) {
        const int flat = threadIdx.x + p * 256;
        const int k = flat >> 3;
        const int cm = (flat & 7) * 4;
        *(ushort4*)&dh[k * SIZE + m0 + cm] = *(ushort4*)&sh[k * 32 + cm];
        *(ushort4*)&dl[k * SIZE + m0 + cm] = *(ushort4*)&sl[k * 32 + cm];
    }
}

// ---------------- prep 2: gate-table coefficients ----------------
__global__ void coef_kernel(const float* __restrict__ wt) {
    const int j = threadIdx.x;
    float p[16];
    float m = -1e30f;
    #pragma unroll
    for (int g = 0; g < 16; g++) { p[g] = wt[g * SIZE + j]; m = fmaxf(m, p[g]); }
    float s = 0.f;
    #pragma unroll
    for (int g = 0; g < 16; g++) { p[g] = expf(p[g] - m); s += p[g]; }
    const float inv = 1.0f / s;
    #pragma unroll
    for (int g = 0; g < 16; g++) p[g] *= inv;
    g_c0[j]  = p[8] + p[9] + p[10] + p[11] + p[12] + p[13] + p[14] + p[15];
    g_cA[j]  = p[2] + p[3] + p[6] + p[7] - p[8] - p[9] - p[12] - p[13];
    g_cB[j]  = p[4] + p[5] + p[6] + p[7] - p[8] - p[9] - p[10] - p[11];
    g_cAB[j] = p[1] - p[2] - p[4] - 2.f * p[6] - p[7]
             + p[8] + 2.f * p[9] + p[11] + p[13] - p[14];
}

// ---------------- main fused kernel ----------------
// One __syncthreads per k-tile. x fp32 staged in REGISTERS (LDG issued during
// previous tile's MMA phase), converted to bf16 hi/lo and STS'd at tile top.
__global__ void __launch_bounds__(256, 2)
fused_logic_mma_kernel(const float* __restrict__ x, float* __restrict__ out) {
    extern __shared__ char smem[];
    const uint32_t sb = smem_u32(smem);
    const int tid = threadIdx.x;
    const int wid = tid >> 5;
    const int lane = tid & 31;
    const int warp_m = wid >> 1;      // 0..3
    const int warp_n = wid & 1;       // 0..1
    const int m0 = blockIdx.y * BM;
    const int n0 = blockIdx.x * BN;

    float accA[2][4][4];
    float accB[2][4][4];
    #pragma unroll
    for (int mt = 0; mt < 2; mt++)
        #pragma unroll
        for (int nt = 0; nt < 4; nt++)
            #pragma unroll
            for (int e = 0; e < 4; e++) { accA[mt][nt][e] = 0.f; accB[mt][nt][e] = 0.f; }

    const __nv_bfloat16* wsrc[4] = { g_wah, g_wal, g_wbh, g_wbl };

    // x register staging: thread owns row (tid>>3), cols (tid&7)*8 .. +7 of the tile
    const int xk = tid >> 3;
    const int xc8 = (tid & 7) * 8;
    const float* xbase = x + (size_t)xk * BATCH + n0 + xc8;
    float4 xs0, xs1;

    auto ldg_x = [&](int kt) {
        const float* src = xbase + (size_t)(kt * BK) * BATCH;
        xs0 = *(const float4*)src;
        xs1 = *(const float4*)(src + 4);
    };
    auto sts_x = [&](int kt) {
        float vv[8] = {xs0.x, xs0.y, xs0.z, xs0.w, xs1.x, xs1.y, xs1.z, xs1.w};
        unsigned short h[8], l[8];
        #pragma unroll
        for (int e = 0; e < 8; e++) {
            __nv_bfloat16 hb = __float2bfloat16(vv[e]);
            __nv_bfloat16 lb = __float2bfloat16(vv[e] - __bfloat162float(hb));
            h[e] = *(unsigned short*)&hb;
            l[e] = *(unsigned short*)&lb;
        }
        char* hrow = smem + (kt & 1) * STAGE_SZ + OFF_XH + xk * XBPAD + xc8 * 2;
        char* lrow = smem + (kt & 1) * STAGE_SZ + OFF_XL + xk * XBPAD + xc8 * 2;
        *(ushort4*)hrow       = make_ushort4(h[0], h[1], h[2], h[3]);
        *(ushort4*)(hrow + 8) = make_ushort4(h[4], h[5], h[6], h[7]);
        *(ushort4*)lrow       = make_ushort4(l[0], l[1], l[2], l[3]);
        *(ushort4*)(lrow + 8) = make_ushort4(l[4], l[5], l[6], l[7]);
    };
    auto issue_w = [&](int kt) {
        const uint32_t base = sb + (kt & 1) * STAGE_SZ;
        // W: 4 variants x 32 k-rows x 16 chunks(16B) = 2048 chunks
        #pragma unroll
        for (int i = 0; i < 8; i++) {
            int flat = tid + i * 256;
            int v = flat >> 9, rem = flat & 511, k = rem >> 4, c = rem & 15;
            const char* src = (const char*)(wsrc[v] + (size_t)(kt * BK + k) * SIZE + m0 + c * 8);
            CP_ASYNC16(base + v * 8704 + k * WKPAD + c * 16, src);
        }
        CP_COMMIT();
    };

    // ldmatrix per-lane address components
    const int g8 = lane >> 3;
    const int r8 = lane & 7;
    const uint32_t w_off = (uint32_t)(((g8 >> 1) * 8 + r8) * WKPAD + (g8 & 1) * 16 + warp_m * 64);
    const uint32_t x_off = (uint32_t)(((g8 & 1) * 8 + r8) * XBPAD + (g8 >> 1) * 16 + warp_n * 64);

    ldg_x(0);
    issue_w(0);
    for (int kt = 0; kt < NUM_KTILES; kt++) {
        const uint32_t base = sb + (kt & 1) * STAGE_SZ;
        CP_WAIT0();                 // W(kt) landed
        sts_x(kt);                  // x(kt) regs -> smem bf16 hi/lo
        __syncthreads();            // the only barrier per k-tile

        if (kt + 1 < NUM_KTILES) {
            ldg_x(kt + 1);          // latency hidden behind MMA phase
            issue_w(kt + 1);        // safe: all threads passed barrier => done with this stage
        }

        #pragma unroll
        for (int ks = 0; ks < 2; ks++) {
            // X fragments: 4 n-tiles x hi/lo (shared by both projections)
            uint32_t xh[4][2], xl[4][2];
            #pragma unroll
            for (int j = 0; j < 2; j++) {
                const uint32_t xo = base + x_off + ks * 16 * XBPAD + j * 32;
                uint32_t r0, r1, r2, r3;
                LDSM_X4_T(r0, r1, r2, r3, xo + OFF_XH);
                xh[2 * j][0] = r0; xh[2 * j][1] = r1;
                xh[2 * j + 1][0] = r2; xh[2 * j + 1][1] = r3;
                LDSM_X4_T(r0, r1, r2, r3, xo + OFF_XL);
                xl[2 * j][0] = r0; xl[2 * j][1] = r1;
                xl[2 * j + 1][0] = r2; xl[2 * j + 1][1] = r3;
            }
            #pragma unroll
            for (int mt = 0; mt < 2; mt++) {
                const uint32_t ao = base + w_off + ks * 16 * WKPAD + mt * 32;
                uint32_t fah[4], fal[4], fbh[4], fbl[4];
                LDSM_X4_T(fah[0], fah[1], fah[2], fah[3], ao + 0);
                LDSM_X4_T(fal[0], fal[1], fal[2], fal[3], ao + 8704);
                LDSM_X4_T(fbh[0], fbh[1], fbh[2], fbh[3], ao + 17408);
                LDSM_X4_T(fbl[0], fbl[1], fbl[2], fbl[3], ao + 26112);
                // term-major order: same-acc reuse distance = 8 MMAs
                #pragma unroll
                for (int nt = 0; nt < 4; nt++) MMA_BF16(accA[mt][nt], fah, xh[nt]);
                #pragma unroll
                for (int nt = 0; nt < 4; nt++) MMA_BF16(accB[mt][nt], fbh, xh[nt]);
                #pragma unroll
                for (int nt = 0; nt < 4; nt++) MMA_BF16(accA[mt][nt], fah, xl[nt]);
                #pragma unroll
                for (int nt = 0; nt < 4; nt++) MMA_BF16(accB[mt][nt], fbh, xl[nt]);
                #pragma unroll
                for (int nt = 0; nt < 4; nt++) MMA_BF16(accA[mt][nt], fal, xh[nt]);
                #pragma unroll
                for (int nt = 0; nt < 4; nt++) MMA_BF16(accB[mt][nt], fbl, xh[nt]);
            }
        }
    }

    // ---- epilogue: out = c0 + cA*A + cB*B + cAB*A*B ----
    const int row_in = lane >> 2;
    const int col2 = (lane & 3) * 2;
    #pragma unroll
    for (int mt = 0; mt < 2; mt++) {
        const int j1 = m0 + warp_m * 32 + mt * 16 + row_in;
        const int j2 = j1 + 8;
        const float c0a = g_c0[j1], cAa = g_cA[j1], cBa = g_cB[j1], cXa = g_cAB[j1];
        const float c0b = g_c0[j2], cAb = g_cA[j2], cBb = g_cB[j2], cXb = g_cAB[j2];
        #pragma unroll
        for (int nt = 0; nt < 4; nt++) {
            const int n = n0 + warp_n * 32 + nt * 8 + col2;
            float2 o1, o2;
            {
                float A = accA[mt][nt][0], B = accB[mt][nt][0];
                o1.x = fmaf(cXa * A, B, fmaf(cAa, A, fmaf(cBa, B, c0a)));
                A = accA[mt][nt][1]; B = accB[mt][nt][1];
                o1.y = fmaf(cXa * A, B, fmaf(cAa, A, fmaf(cBa, B, c0a)));
            }
            {
                float A = accA[mt][nt][2], B = accB[mt][nt][2];
                o2.x = fmaf(cXb * A, B, fmaf(cAb, A, fmaf(cBb, B, c0b)));
                A = accA[mt][nt][3]; B = accB[mt][nt][3];
                o2.y = fmaf(cXb * A, B, fmaf(cAb, A, fmaf(cBb, B, c0b)));
            }
            *(float2*)&out[(size_t)j1 * BATCH + n] = o1;
            *(float2*)&out[(size_t)j2 * BATCH + n] = o2;
        }
    }
}

// ---------------- launch ----------------
extern "C" void kernel_launch(void* const* d_in, const int* in_sizes, int n_in,
                              void* d_out, int out_size) {
    const float* x  = (const float*)d_in[0];   // [PREV,  BATCH]
    const float* wa = (const float*)d_in[1];   // [SIZE,  PREV]
    const float* wb = (const float*)d_in[2];   // [SIZE,  PREV]
    const float* wt = (const float*)d_in[3];   // [16,    SIZE]
    float* out = (float*)d_out;                // [SIZE,  BATCH]

    cudaFuncSetAttribute(fused_logic_mma_kernel,
                         cudaFuncAttributeMaxDynamicSharedMemorySize, SMEM_TOTAL);

    softmax_rows_kernel<<<16, 256>>>(wa, wb);
    coef_kernel<<<1, 256>>>(wt);

    dim3 grid(BATCH / BN, SIZE / BM);  // (512, 2)
    fused_logic_mma_kernel<<<grid, 256, SMEM_TOTAL>>>(x, out);
}

// round 7
// speedup vs baseline: 4.3748x; 1.7846x over previous
#include <cuda_runtime.h>
#include <cuda_fp16.h>
#include <cstdint>

#define SIZE  256
#define PREV  256
#define BATCH 32768

#define BM 128
#define BN 64
#define BK 32
#define NUM_KTILES (PREV / BK)   // 8
#define NTILES ((BATCH / BN) * (SIZE / BM))   // 1024
#define NCTA 296                 // 2 per SM x 148 SMs

// ---------------- scratch ----------------
// W arrays stored TRANSPOSED (k-major) fp16: g_w*[k][m]
__device__ __align__(128) __half g_wa[PREV * SIZE];
__device__ __align__(128) __half g_wb[PREV * SIZE];
__device__ float g_c0[SIZE];
__device__ float g_cA[SIZE];
__device__ float g_cB[SIZE];
__device__ float g_cAB[SIZE];

// ---------------- smem layout (bytes, per stage) ----------------
// W tiles (k-major): 32 k-rows x 128 m x 2B = 256B/row, pad 272 -> 8704 each (x2: wa, wb)
// X fp16 tile:       32 k-rows x 64 n x 2B = 128B/row, pad 144 -> 4608
#define WKPAD 272
#define XBPAD 144
#define OFF_WB  8704
#define OFF_X   17408
#define STAGE_SZ 22016
#define SMEM_TOTAL (2 * STAGE_SZ)   // 44032

// ============================ PTX helpers ============================
__device__ __forceinline__ uint32_t smem_u32(const void* p) {
    uint32_t a;
    asm("{ .reg .u64 t; cvta.to.shared.u64 t, %1; cvt.u32.u64 %0, t; }" : "=r"(a) : "l"(p));
    return a;
}
#define CP_ASYNC16(dst, src) \
    asm volatile("cp.async.cg.shared.global [%0], [%1], 16;" :: "r"(dst), "l"(src))
#define CP_COMMIT() asm volatile("cp.async.commit_group;" ::: "memory")
#define CP_WAIT0()  asm volatile("cp.async.wait_group 0;" ::: "memory")

#define LDSM_X4_T(r0, r1, r2, r3, addr)                                         \
    asm volatile("ldmatrix.sync.aligned.m8n8.x4.trans.shared.b16 {%0,%1,%2,%3}, [%4];" \
                 : "=r"(r0), "=r"(r1), "=r"(r2), "=r"(r3) : "r"(addr))

#define MMA_F16(c, a, b)                                                        \
    asm volatile("mma.sync.aligned.m16n8k16.row.col.f32.f16.f16.f32 "           \
                 "{%0,%1,%2,%3}, {%4,%5,%6,%7}, {%8,%9}, {%0,%1,%2,%3};"        \
                 : "+f"((c)[0]), "+f"((c)[1]), "+f"((c)[2]), "+f"((c)[3])       \
                 : "r"((a)[0]), "r"((a)[1]), "r"((a)[2]), "r"((a)[3]),          \
                   "r"((b)[0]), "r"((b)[1]))

// ---------------- prep 1: row softmax -> transposed fp16 ----------------
// 64 blocks x 8 warps; each warp reduces one row; smem transpose; 16B writes.
__global__ void softmax_rows_kernel(const float* __restrict__ wa,
                                    const float* __restrict__ wb) {
    __shared__ unsigned short sh[PREV * 8];   // [k][mloc]
    const int bx = blockIdx.x;
    const float* src = (bx < 32) ? wa : wb;
    __half* dst = (bx < 32) ? g_wa : g_wb;
    const int m0 = (bx & 31) * 8;
    const int wid = threadIdx.x >> 5;   // row within block (0..7)
    const int lane = threadIdx.x & 31;

    const float* row = src + (size_t)(m0 + wid) * PREV;
    float v[8];
    float mx = -1e30f;
    #pragma unroll
    for (int i = 0; i < 8; i++) { v[i] = row[lane + 32 * i]; mx = fmaxf(mx, v[i]); }
    #pragma unroll
    for (int o = 16; o; o >>= 1) mx = fmaxf(mx, __shfl_xor_sync(0xffffffffu, mx, o));
    float e[8], s = 0.f;
    #pragma unroll
    for (int i = 0; i < 8; i++) { e[i] = expf(v[i] - mx); s += e[i]; }
    #pragma unroll
    for (int o = 16; o; o >>= 1) s += __shfl_xor_sync(0xffffffffu, s, o);
    const float inv = 1.0f / s;
    #pragma unroll
    for (int i = 0; i < 8; i++) {
        __half h = __float2half_rn(e[i] * inv);
        sh[(lane + 32 * i) * 8 + wid] = *(unsigned short*)&h;
    }
    __syncthreads();
    // thread t writes row k=t: 8 m entries = 16B chunk
    const int k = threadIdx.x;
    *(uint4*)&dst[(size_t)k * SIZE + m0] = *(uint4*)&sh[k * 8];
}

// ---------------- prep 2: gate-table coefficients ----------------
__global__ void coef_kernel(const float* __restrict__ wt) {
    const int j = threadIdx.x;
    float p[16];
    float m = -1e30f;
    #pragma unroll
    for (int g = 0; g < 16; g++) { p[g] = wt[g * SIZE + j]; m = fmaxf(m, p[g]); }
    float s = 0.f;
    #pragma unroll
    for (int g = 0; g < 16; g++) { p[g] = expf(p[g] - m); s += p[g]; }
    const float inv = 1.0f / s;
    #pragma unroll
    for (int g = 0; g < 16; g++) p[g] *= inv;
    g_c0[j]  = p[8] + p[9] + p[10] + p[11] + p[12] + p[13] + p[14] + p[15];
    g_cA[j]  = p[2] + p[3] + p[6] + p[7] - p[8] - p[9] - p[12] - p[13];
    g_cB[j]  = p[4] + p[5] + p[6] + p[7] - p[8] - p[9] - p[10] - p[11];
    g_cAB[j] = p[1] - p[2] - p[4] - 2.f * p[6] - p[7]
             + p[8] + 2.f * p[9] + p[11] + p[13] - p[14];
}

// ---------------- main fused kernel (persistent, fp16 single-term) ----------------
__global__ void __launch_bounds__(256, 2)
fused_logic_mma_kernel(const float* __restrict__ x, float* __restrict__ out) {
    extern __shared__ char smem[];
    const uint32_t sb = smem_u32(smem);
    const int tid = threadIdx.x;
    const int wid = tid >> 5;
    const int lane = tid & 31;
    const int warp_m = wid >> 1;      // 0..3
    const int warp_n = wid & 1;       // 0..1

    float accA[2][4][4];
    float accB[2][4][4];
    #pragma unroll
    for (int mt = 0; mt < 2; mt++)
        #pragma unroll
        for (int nt = 0; nt < 4; nt++)
            #pragma unroll
            for (int e = 0; e < 4; e++) { accA[mt][nt][e] = 0.f; accB[mt][nt][e] = 0.f; }

    // x register staging: thread owns tile-row (tid>>3), cols (tid&7)*8..+7
    const int xk = tid >> 3;
    const int xc8 = (tid & 7) * 8;
    float4 xs0, xs1;

    auto ldg_x = [&](int n0, int kt) {
        const float* src = x + (size_t)(kt * BK + xk) * BATCH + n0 + xc8;
        xs0 = *(const float4*)src;
        xs1 = *(const float4*)(src + 4);
    };
    auto sts_x = [&](int stage) {
        float vv[8] = {xs0.x, xs0.y, xs0.z, xs0.w, xs1.x, xs1.y, xs1.z, xs1.w};
        unsigned short h[8];
        #pragma unroll
        for (int e = 0; e < 8; e++) {
            __half hb = __float2half_rn(vv[e]);
            h[e] = *(unsigned short*)&hb;
        }
        char* hrow = smem + stage * STAGE_SZ + OFF_X + xk * XBPAD + xc8 * 2;
        *(ushort4*)hrow       = make_ushort4(h[0], h[1], h[2], h[3]);
        *(ushort4*)(hrow + 8) = make_ushort4(h[4], h[5], h[6], h[7]);
    };
    auto issue_w = [&](int m0, int kt, int stage) {
        const uint32_t base = sb + stage * STAGE_SZ;
        // 2 variants x 32 k-rows x 16 chunks(16B) = 1024 chunks
        #pragma unroll
        for (int i = 0; i < 4; i++) {
            int flat = tid + i * 256;
            int v = flat >> 9, rem = flat & 511, k = rem >> 4, c = rem & 15;
            const __half* wp = v ? g_wb : g_wa;
            const char* src = (const char*)(wp + (size_t)(kt * BK + k) * SIZE + m0 + c * 8);
            CP_ASYNC16(base + v * OFF_WB + k * WKPAD + c * 16, src);
        }
        CP_COMMIT();
    };

    // ldmatrix per-lane address components
    const int g8 = lane >> 3;
    const int r8 = lane & 7;
    const uint32_t w_off = (uint32_t)(((g8 >> 1) * 8 + r8) * WKPAD + (g8 & 1) * 16 + warp_m * 64);
    const uint32_t x_off = (uint32_t)(((g8 & 1) * 8 + r8) * XBPAD + (g8 >> 1) * 16 + warp_n * 64);

    int tile = blockIdx.x;                 // < NCTA <= NTILES
    int m0 = (tile & 1) * BM;
    int n0 = (tile >> 1) * BN;

    ldg_x(n0, 0);
    issue_w(m0, 0, 0);
    int step = 0;

    while (true) {
        #pragma unroll 1
        for (int kt = 0; kt < NUM_KTILES; kt++) {
            const int stage = step & 1;
            const uint32_t base = sb + stage * STAGE_SZ;
            CP_WAIT0();
            sts_x(stage);
            __syncthreads();               // single barrier per step

            // prefetch next step (next k-tile, or next tile's k0)
            int nkt = kt + 1, ntile = tile;
            if (nkt == NUM_KTILES) { nkt = 0; ntile = tile + NCTA; }
            if (ntile < NTILES) {
                const int nm0 = (ntile & 1) * BM;
                const int nn0 = (ntile >> 1) * BN;
                ldg_x(nn0, nkt);
                issue_w(nm0, nkt, (step + 1) & 1);
            }

            #pragma unroll
            for (int ks = 0; ks < 2; ks++) {
                uint32_t xf[4][2];
                #pragma unroll
                for (int j = 0; j < 2; j++) {
                    const uint32_t xo = base + x_off + ks * 16 * XBPAD + j * 32 + OFF_X;
                    uint32_t r0, r1, r2, r3;
                    LDSM_X4_T(r0, r1, r2, r3, xo);
                    xf[2 * j][0] = r0; xf[2 * j][1] = r1;
                    xf[2 * j + 1][0] = r2; xf[2 * j + 1][1] = r3;
                }
                #pragma unroll
                for (int mt = 0; mt < 2; mt++) {
                    const uint32_t ao = base + w_off + ks * 16 * WKPAD + mt * 32;
                    uint32_t fa[4], fb[4];
                    LDSM_X4_T(fa[0], fa[1], fa[2], fa[3], ao);
                    LDSM_X4_T(fb[0], fb[1], fb[2], fb[3], ao + OFF_WB);
                    #pragma unroll
                    for (int nt = 0; nt < 4; nt++) MMA_F16(accA[mt][nt], fa, xf[nt]);
                    #pragma unroll
                    for (int nt = 0; nt < 4; nt++) MMA_F16(accB[mt][nt], fb, xf[nt]);
                }
            }
            step++;
        }

        // ---- epilogue: out = c0 + cA*A + cB*B + cAB*A*B; re-zero accs ----
        {
            const int row_in = lane >> 2;
            const int col2 = (lane & 3) * 2;
            #pragma unroll
            for (int mt = 0; mt < 2; mt++) {
                const int j1 = m0 + warp_m * 32 + mt * 16 + row_in;
                const int j2 = j1 + 8;
                const float c0a = g_c0[j1], cAa = g_cA[j1], cBa = g_cB[j1], cXa = g_cAB[j1];
                const float c0b = g_c0[j2], cAb = g_cA[j2], cBb = g_cB[j2], cXb = g_cAB[j2];
                #pragma unroll
                for (int nt = 0; nt < 4; nt++) {
                    const int n = n0 + warp_n * 32 + nt * 8 + col2;
                    float2 o1, o2;
                    {
                        float A = accA[mt][nt][0], B = accB[mt][nt][0];
                        o1.x = fmaf(cXa * A, B, fmaf(cAa, A, fmaf(cBa, B, c0a)));
                        A = accA[mt][nt][1]; B = accB[mt][nt][1];
                        o1.y = fmaf(cXa * A, B, fmaf(cAa, A, fmaf(cBa, B, c0a)));
                    }
                    {
                        float A = accA[mt][nt][2], B = accB[mt][nt][2];
                        o2.x = fmaf(cXb * A, B, fmaf(cAb, A, fmaf(cBb, B, c0b)));
                        A = accA[mt][nt][3]; B = accB[mt][nt][3];
                        o2.y = fmaf(cXb * A, B, fmaf(cAb, A, fmaf(cBb, B, c0b)));
                    }
                    *(float2*)&out[(size_t)j1 * BATCH + n] = o1;
                    *(float2*)&out[(size_t)j2 * BATCH + n] = o2;
                    #pragma unroll
                    for (int e = 0; e < 4; e++) { accA[mt][nt][e] = 0.f; accB[mt][nt][e] = 0.f; }
                }
            }
        }

        tile += NCTA;
        if (tile >= NTILES) break;
        m0 = (tile & 1) * BM;
        n0 = (tile >> 1) * BN;
    }
}

// ---------------- launch ----------------
extern "C" void kernel_launch(void* const* d_in, const int* in_sizes, int n_in,
                              void* d_out, int out_size) {
    const float* x  = (const float*)d_in[0];   // [PREV,  BATCH]
    const float* wa = (const float*)d_in[1];   // [SIZE,  PREV]
    const float* wb = (const float*)d_in[2];   // [SIZE,  PREV]
    const float* wt = (const float*)d_in[3];   // [16,    SIZE]
    float* out = (float*)d_out;                // [SIZE,  BATCH]

    cudaFuncSetAttribute(fused_logic_mma_kernel,
                         cudaFuncAttributeMaxDynamicSharedMemorySize, SMEM_TOTAL);

    softmax_rows_kernel<<<64, 256>>>(wa, wb);
    coef_kernel<<<1, 256>>>(wt);
    fused_logic_mma_kernel<<<NCTA, 256, SMEM_TOTAL>>>(x, out);
}

// round 8
// speedup vs baseline: 4.5617x; 1.0427x over previous
#include <cuda_runtime.h>
#include <cuda_fp16.h>
#include <cstdint>

#define SIZE  256
#define PREV  256
#define BATCH 32768

#define BM 128
#define BN 64
#define BK 32
#define NUM_KTILES (PREV / BK)                // 8
#define NTILES ((BATCH / BN) * (SIZE / BM))   // 1024
#define NCTA 296                              // 2/SM x 148 SMs

// ---------------- scratch ----------------
__device__ __align__(128) __half g_wa[PREV * SIZE];   // k-major [k][m]
__device__ __align__(128) __half g_wb[PREV * SIZE];
__device__ float g_c0[SIZE];
__device__ float g_cA[SIZE];
__device__ float g_cB[SIZE];
__device__ float g_cAB[SIZE];

// ---------------- smem layout ----------------
// W stage: 2 variants x (32 k-rows x 256B, pad 272) = 17408 B;  4 stages
// X stage: 32 k-rows x 128B, pad 144 = 4608 B;                  2 stages
#define WKPAD 272
#define XBPAD 144
#define W_STAGE 17408
#define OFF_X   (4 * W_STAGE)        // 69632
#define X_STAGE 4608
#define SMEM_TOTAL (OFF_X + 2 * X_STAGE)   // 78848

// ============================ PTX helpers ============================
__device__ __forceinline__ uint32_t smem_u32(const void* p) {
    uint32_t a;
    asm("{ .reg .u64 t; cvta.to.shared.u64 t, %1; cvt.u32.u64 %0, t; }" : "=r"(a) : "l"(p));
    return a;
}
#define CP_ASYNC16(dst, src) \
    asm volatile("cp.async.cg.shared.global [%0], [%1], 16;" :: "r"(dst), "l"(src))
#define CP_COMMIT() asm volatile("cp.async.commit_group;" ::: "memory")
#define CP_WAIT2()  asm volatile("cp.async.wait_group 2;" ::: "memory")

#define LDSM_X4_T(r0, r1, r2, r3, addr)                                         \
    asm volatile("ldmatrix.sync.aligned.m8n8.x4.trans.shared.b16 {%0,%1,%2,%3}, [%4];" \
                 : "=r"(r0), "=r"(r1), "=r"(r2), "=r"(r3) : "r"(addr))

#define MMA_F16(c, a, b)                                                        \
    asm volatile("mma.sync.aligned.m16n8k16.row.col.f32.f16.f16.f32 "           \
                 "{%0,%1,%2,%3}, {%4,%5,%6,%7}, {%8,%9}, {%0,%1,%2,%3};"        \
                 : "+f"((c)[0]), "+f"((c)[1]), "+f"((c)[2]), "+f"((c)[3])       \
                 : "r"((a)[0]), "r"((a)[1]), "r"((a)[2]), "r"((a)[3]),          \
                   "r"((b)[0]), "r"((b)[1]))

// ---------------- prep: softmax rows -> transposed fp16 (+ coefs in block 0) ----------------
__global__ void prep_kernel(const float* __restrict__ wa, const float* __restrict__ wb,
                            const float* __restrict__ wt) {
    __shared__ unsigned short sh[PREV * 8];
    const int bx = blockIdx.x;
    const float* src = (bx < 32) ? wa : wb;
    __half* dst = (bx < 32) ? g_wa : g_wb;
    const int m0 = (bx & 31) * 8;
    const int wid = threadIdx.x >> 5;
    const int lane = threadIdx.x & 31;

    const float* row = src + (size_t)(m0 + wid) * PREV;
    float v[8];
    float mx = -1e30f;
    #pragma unroll
    for (int i = 0; i < 8; i++) { v[i] = row[lane + 32 * i]; mx = fmaxf(mx, v[i]); }
    #pragma unroll
    for (int o = 16; o; o >>= 1) mx = fmaxf(mx, __shfl_xor_sync(0xffffffffu, mx, o));
    float e[8], s = 0.f;
    #pragma unroll
    for (int i = 0; i < 8; i++) { e[i] = expf(v[i] - mx); s += e[i]; }
    #pragma unroll
    for (int o = 16; o; o >>= 1) s += __shfl_xor_sync(0xffffffffu, s, o);
    const float inv = 1.0f / s;
    #pragma unroll
    for (int i = 0; i < 8; i++) {
        __half h = __float2half_rn(e[i] * inv);
        sh[(lane + 32 * i) * 8 + wid] = *(unsigned short*)&h;
    }

    // block 0 additionally computes the gate-table coefficients
    if (bx == 0) {
        const int j = threadIdx.x;
        float p[16];
        float m = -1e30f;
        #pragma unroll
        for (int g = 0; g < 16; g++) { p[g] = wt[g * SIZE + j]; m = fmaxf(m, p[g]); }
        float ss = 0.f;
        #pragma unroll
        for (int g = 0; g < 16; g++) { p[g] = expf(p[g] - m); ss += p[g]; }
        const float iv = 1.0f / ss;
        #pragma unroll
        for (int g = 0; g < 16; g++) p[g] *= iv;
        g_c0[j]  = p[8] + p[9] + p[10] + p[11] + p[12] + p[13] + p[14] + p[15];
        g_cA[j]  = p[2] + p[3] + p[6] + p[7] - p[8] - p[9] - p[12] - p[13];
        g_cB[j]  = p[4] + p[5] + p[6] + p[7] - p[8] - p[9] - p[10] - p[11];
        g_cAB[j] = p[1] - p[2] - p[4] - 2.f * p[6] - p[7]
                 + p[8] + 2.f * p[9] + p[11] + p[13] - p[14];
    }

    __syncthreads();
    const int k = threadIdx.x;
    *(uint4*)&dst[(size_t)k * SIZE + m0] = *(uint4*)&sh[k * 8];
}

// ---------------- main fused kernel (persistent, 4-stage W ring, 2-stage X ring) ----------------
__global__ void __launch_bounds__(256, 2)
fused_logic_mma_kernel(const float* __restrict__ x, float* __restrict__ out) {
    extern __shared__ char smem[];
    const uint32_t sb = smem_u32(smem);
    const int tid = threadIdx.x;
    const int wid = tid >> 5;
    const int lane = tid & 31;
    const int warp_m = wid >> 1;
    const int warp_n = wid & 1;
    const int bid = blockIdx.x;

    float accA[2][4][4];
    float accB[2][4][4];
    #pragma unroll
    for (int mt = 0; mt < 2; mt++)
        #pragma unroll
        for (int nt = 0; nt < 4; nt++)
            #pragma unroll
            for (int e = 0; e < 4; e++) { accA[mt][nt][e] = 0.f; accB[mt][nt][e] = 0.f; }

    const int xk = tid >> 3;
    const int xc8 = (tid & 7) * 8;
    float r0v[8], r1v[8];

    auto ldg_x = [&](float (&r)[8], int n0, int kt) {
        const float* src = x + (size_t)(kt * BK + xk) * BATCH + n0 + xc8;
        float4 a = *(const float4*)src;
        float4 b = *(const float4*)(src + 4);
        r[0] = a.x; r[1] = a.y; r[2] = a.z; r[3] = a.w;
        r[4] = b.x; r[5] = b.y; r[6] = b.z; r[7] = b.w;
    };
    auto sts_x = [&](float (&r)[8], int xstage) {
        unsigned short h[8];
        #pragma unroll
        for (int e = 0; e < 8; e++) {
            __half hb = __float2half_rn(r[e]);
            h[e] = *(unsigned short*)&hb;
        }
        char* hrow = smem + OFF_X + xstage * X_STAGE + xk * XBPAD + xc8 * 2;
        *(ushort4*)hrow       = make_ushort4(h[0], h[1], h[2], h[3]);
        *(ushort4*)(hrow + 8) = make_ushort4(h[4], h[5], h[6], h[7]);
    };
    auto issue_w = [&](int m0, int kt, int wstage) {
        const uint32_t base = sb + wstage * W_STAGE;
        #pragma unroll
        for (int i = 0; i < 4; i++) {
            int flat = tid + i * 256;
            int v = flat >> 9, rem = flat & 511, k = rem >> 4, c = rem & 15;
            const __half* wp = v ? g_wb : g_wa;
            const char* src = (const char*)(wp + (size_t)(kt * BK + k) * SIZE + m0 + c * 8);
            CP_ASYNC16(base + v * 8704 + k * WKPAD + c * 16, src);
        }
    };

    const int g8 = lane >> 3;
    const int r8 = lane & 7;
    const uint32_t w_off = (uint32_t)(((g8 >> 1) * 8 + r8) * WKPAD + (g8 & 1) * 16 + warp_m * 64);
    const uint32_t x_off = (uint32_t)(((g8 & 1) * 8 + r8) * XBPAD + (g8 >> 1) * 16 + warp_n * 64);

    const int ntiles = (NTILES - bid + NCTA - 1) / NCTA;
    const int Q = ntiles * 8;

    // prologue (Q >= 8 always; tiles for q=0..2 are all tile bid)
    {
        const int m0 = (bid & 1) * BM;
        const int n0 = (bid >> 1) * BN;
        ldg_x(r0v, n0, 0);
        ldg_x(r1v, n0, 1);
        issue_w(m0, 0, 0); CP_COMMIT();
        issue_w(m0, 1, 1); CP_COMMIT();
        issue_w(m0, 2, 2); CP_COMMIT();
        sts_x(r0v, 0);
    }

    auto body = [&](int q, float (&ld)[8], float (&st)[8]) {
        const int kt = q & 7;
        const int tile = bid + (q >> 3) * NCTA;
        const int m0 = (tile & 1) * BM;
        const int n0 = (tile >> 1) * BN;
        const uint32_t wbase = sb + (q & 3) * W_STAGE;
        const uint32_t xbase = sb + OFF_X + (q & 1) * X_STAGE;

        CP_WAIT2();          // W(q) done (committed 3 steps ago)
        __syncthreads();     // publish W(q) + X(q)

        // stage future work (overlapped with MMA phase below)
        const int q1 = q + 1;
        if (q1 < Q) sts_x(st, q1 & 1);
        const int q2 = q + 2;
        if (q2 < Q) {
            const int t2 = bid + (q2 >> 3) * NCTA;
            ldg_x(ld, (t2 >> 1) * BN, q2 & 7);
        }
        const int q3 = q + 3;
        if (q3 < Q) {
            const int t3 = bid + (q3 >> 3) * NCTA;
            issue_w((t3 & 1) * BM, q3 & 7, q3 & 3);
        }
        CP_COMMIT();         // always commit (empty group near the end keeps accounting)

        #pragma unroll
        for (int ks = 0; ks < 2; ks++) {
            uint32_t xf[4][2];
            #pragma unroll
            for (int j = 0; j < 2; j++) {
                const uint32_t xo = xbase + x_off + ks * 16 * XBPAD + j * 32;
                uint32_t a0, a1, a2, a3;
                LDSM_X4_T(a0, a1, a2, a3, xo);
                xf[2 * j][0] = a0; xf[2 * j][1] = a1;
                xf[2 * j + 1][0] = a2; xf[2 * j + 1][1] = a3;
            }
            #pragma unroll
            for (int mt = 0; mt < 2; mt++) {
                const uint32_t ao = wbase + w_off + ks * 16 * WKPAD + mt * 32;
                uint32_t fa[4], fb[4];
                LDSM_X4_T(fa[0], fa[1], fa[2], fa[3], ao);
                LDSM_X4_T(fb[0], fb[1], fb[2], fb[3], ao + 8704);
                #pragma unroll
                for (int nt = 0; nt < 4; nt++) MMA_F16(accA[mt][nt], fa, xf[nt]);
                #pragma unroll
                for (int nt = 0; nt < 4; nt++) MMA_F16(accB[mt][nt], fb, xf[nt]);
            }
        }

        if (kt == 7) {
            // epilogue for this tile, then zero accumulators
            const int row_in = lane >> 2;
            const int col2 = (lane & 3) * 2;
            #pragma unroll
            for (int mt = 0; mt < 2; mt++) {
                const int j1 = m0 + warp_m * 32 + mt * 16 + row_in;
                const int j2 = j1 + 8;
                const float c0a = g_c0[j1], cAa = g_cA[j1], cBa = g_cB[j1], cXa = g_cAB[j1];
                const float c0b = g_c0[j2], cAb = g_cA[j2], cBb = g_cB[j2], cXb = g_cAB[j2];
                #pragma unroll
                for (int nt = 0; nt < 4; nt++) {
                    const int n = n0 + warp_n * 32 + nt * 8 + col2;
                    float2 o1, o2;
                    {
                        float A = accA[mt][nt][0], B = accB[mt][nt][0];
                        o1.x = fmaf(cXa * A, B, fmaf(cAa, A, fmaf(cBa, B, c0a)));
                        A = accA[mt][nt][1]; B = accB[mt][nt][1];
                        o1.y = fmaf(cXa * A, B, fmaf(cAa, A, fmaf(cBa, B, c0a)));
                    }
                    {
                        float A = accA[mt][nt][2], B = accB[mt][nt][2];
                        o2.x = fmaf(cXb * A, B, fmaf(cAb, A, fmaf(cBb, B, c0b)));
                        A = accA[mt][nt][3]; B = accB[mt][nt][3];
                        o2.y = fmaf(cXb * A, B, fmaf(cAb, A, fmaf(cBb, B, c0b)));
                    }
                    *(float2*)&out[(size_t)j1 * BATCH + n] = o1;
                    *(float2*)&out[(size_t)j2 * BATCH + n] = o2;
                    #pragma unroll
                    for (int e = 0; e < 4; e++) { accA[mt][nt][e] = 0.f; accB[mt][nt][e] = 0.f; }
                }
            }
        }
    };

    #pragma unroll 1
    for (int q = 0; q < Q; q += 2) {
        body(q,     r0v, r1v);   // LDG(q+2)->r0, STS X(q+1) from r1
        body(q + 1, r1v, r0v);   // LDG(q+3)->r1, STS X(q+2) from r0
    }
}

// ---------------- launch ----------------
extern "C" void kernel_launch(void* const* d_in, const int* in_sizes, int n_in,
                              void* d_out, int out_size) {
    const float* x  = (const float*)d_in[0];   // [PREV,  BATCH]
    const float* wa = (const float*)d_in[1];   // [SIZE,  PREV]
    const float* wb = (const float*)d_in[2];   // [SIZE,  PREV]
    const float* wt = (const float*)d_in[3];   // [16,    SIZE]
    float* out = (float*)d_out;                // [SIZE,  BATCH]

    cudaFuncSetAttribute(fused_logic_mma_kernel,
                         cudaFuncAttributeMaxDynamicSharedMemorySize, SMEM_TOTAL);

    prep_kernel<<<64, 256>>>(wa, wb, wt);
    fused_logic_mma_kernel<<<NCTA, 256, SMEM_TOTAL>>>(x, out);
}

// round 9
// speedup vs baseline: 4.7756x; 1.0469x over previous
#include <cuda_runtime.h>
#include <cuda_fp16.h>
#include <cstdint>

#define SIZE  256
#define PREV  256
#define BATCH 32768

#define BM 128
#define BN 128
#define BK 32
#define NUM_KTILES (PREV / BK)       // 8
#define N_NTILES (BATCH / BN)        // 256
#define NCTA 148
#define HALF_CTAS (NCTA / 2)         // 74

// ---------------- scratch ----------------
__device__ __align__(128) __half g_wa[PREV * SIZE];   // k-major [k][m]
__device__ __align__(128) __half g_wb[PREV * SIZE];
__device__ float g_c0[SIZE];
__device__ float g_cA[SIZE];
__device__ float g_cB[SIZE];
__device__ float g_cAB[SIZE];

// ---------------- smem layout ----------------
// W resident: 2 proj x 256 k-rows x (128 m x 2B = 256B, pad 272) = 69632 each
// X ring: 2 stages x (32 k-rows x (128 n x 2B = 256B, pad 272)) = 8704 each
#define WKPAD 272
#define XBPAD 272
#define W_PROJ 69632
#define OFF_X  (2 * W_PROJ)                 // 139264
#define X_STAGE 8704
#define SMEM_TOTAL (OFF_X + 2 * X_STAGE)    // 156672

// ============================ PTX helpers ============================
__device__ __forceinline__ uint32_t smem_u32(const void* p) {
    uint32_t a;
    asm("{ .reg .u64 t; cvta.to.shared.u64 t, %1; cvt.u32.u64 %0, t; }" : "=r"(a) : "l"(p));
    return a;
}
#define CP_ASYNC16(dst, src) \
    asm volatile("cp.async.cg.shared.global [%0], [%1], 16;" :: "r"(dst), "l"(src))
#define CP_COMMIT() asm volatile("cp.async.commit_group;" ::: "memory")
#define CP_WAIT0()  asm volatile("cp.async.wait_group 0;" ::: "memory")

#define LDSM_X4_T(r0, r1, r2, r3, addr)                                         \
    asm volatile("ldmatrix.sync.aligned.m8n8.x4.trans.shared.b16 {%0,%1,%2,%3}, [%4];" \
                 : "=r"(r0), "=r"(r1), "=r"(r2), "=r"(r3) : "r"(addr))

#define MMA_F16(c, a, b)                                                        \
    asm volatile("mma.sync.aligned.m16n8k16.row.col.f32.f16.f16.f32 "           \
                 "{%0,%1,%2,%3}, {%4,%5,%6,%7}, {%8,%9}, {%0,%1,%2,%3};"        \
                 : "+f"((c)[0]), "+f"((c)[1]), "+f"((c)[2]), "+f"((c)[3])       \
                 : "r"((a)[0]), "r"((a)[1]), "r"((a)[2]), "r"((a)[3]),          \
                   "r"((b)[0]), "r"((b)[1]))

// ---------------- prep: softmax rows -> transposed fp16 (+ coefs in blocks 0,1) ----------------
// 128 blocks x 128 threads; block handles 4 rows (warp per row).
__global__ void prep_kernel(const float* __restrict__ wa, const float* __restrict__ wb,
                            const float* __restrict__ wt) {
    __shared__ unsigned short sh[PREV * 4];
    const int bx = blockIdx.x;
    const float* src = (bx < 64) ? wa : wb;
    __half* dst = (bx < 64) ? g_wa : g_wb;
    const int m0 = (bx & 63) * 4;
    const int wid = threadIdx.x >> 5;   // row 0..3
    const int lane = threadIdx.x & 31;

    const float* row = src + (size_t)(m0 + wid) * PREV;
    float v[8];
    float mx = -1e30f;
    #pragma unroll
    for (int i = 0; i < 8; i++) { v[i] = row[lane + 32 * i]; mx = fmaxf(mx, v[i]); }
    #pragma unroll
    for (int o = 16; o; o >>= 1) mx = fmaxf(mx, __shfl_xor_sync(0xffffffffu, mx, o));
    float e[8], s = 0.f;
    #pragma unroll
    for (int i = 0; i < 8; i++) { e[i] = expf(v[i] - mx); s += e[i]; }
    #pragma unroll
    for (int o = 16; o; o >>= 1) s += __shfl_xor_sync(0xffffffffu, s, o);
    const float inv = 1.0f / s;
    #pragma unroll
    for (int i = 0; i < 8; i++) {
        __half h = __float2half_rn(e[i] * inv);
        sh[(lane + 32 * i) * 4 + wid] = *(unsigned short*)&h;
    }

    if (bx < 2) {   // coefs: j = bx*128 + tid
        const int j = bx * 128 + threadIdx.x;
        float p[16];
        float m = -1e30f;
        #pragma unroll
        for (int g = 0; g < 16; g++) { p[g] = wt[g * SIZE + j]; m = fmaxf(m, p[g]); }
        float ss = 0.f;
        #pragma unroll
        for (int g = 0; g < 16; g++) { p[g] = expf(p[g] - m); ss += p[g]; }
        const float iv = 1.0f / ss;
        #pragma unroll
        for (int g = 0; g < 16; g++) p[g] *= iv;
        g_c0[j]  = p[8] + p[9] + p[10] + p[11] + p[12] + p[13] + p[14] + p[15];
        g_cA[j]  = p[2] + p[3] + p[6] + p[7] - p[8] - p[9] - p[12] - p[13];
        g_cB[j]  = p[4] + p[5] + p[6] + p[7] - p[8] - p[9] - p[10] - p[11];
        g_cAB[j] = p[1] - p[2] - p[4] - 2.f * p[6] - p[7]
                 + p[8] + 2.f * p[9] + p[11] + p[13] - p[14];
    }

    __syncthreads();
    // 256 rows x 4 m = 8B chunks; 128 threads do 2 each
    const int t = threadIdx.x;
    *(ushort4*)&dst[(size_t)t * SIZE + m0]         = *(ushort4*)&sh[t * 4];
    *(ushort4*)&dst[(size_t)(t + 128) * SIZE + m0] = *(ushort4*)&sh[(t + 128) * 4];
}

// ---------------- main kernel: W-resident persistent GEMM ----------------
// 148 CTAs, 1/SM. CTA pinned to m-half (bid&1); W for that half loaded to smem once.
// 8 warps as 4(m) x 2(n); warp tile 32m x 64n (nt=8). Steady state: only X moves.
__global__ void __launch_bounds__(256, 1)
fused_logic_mma_kernel(const float* __restrict__ x, float* __restrict__ out) {
    extern __shared__ char smem[];
    const uint32_t sb = smem_u32(smem);
    const int tid = threadIdx.x;
    const int wid = tid >> 5;
    const int lane = tid & 31;
    const int warp_m = wid >> 1;      // 0..3
    const int warp_n = wid & 1;       // 0..1
    const int bid = blockIdx.x;
    const int m0 = (bid & 1) * BM;
    const int nbase = bid >> 1;       // 0..73

    // number of n-tiles for this CTA: n_idx = nbase + 74*j < 256
    const int ntiles = (N_NTILES - 1 - nbase) / HALF_CTAS + 1;   // 3 or 4
    const int Q = ntiles * NUM_KTILES;

    float accA[2][8][4];
    float accB[2][8][4];
    #pragma unroll
    for (int mt = 0; mt < 2; mt++)
        #pragma unroll
        for (int nt = 0; nt < 8; nt++)
            #pragma unroll
            for (int e = 0; e < 4; e++) { accA[mt][nt][e] = 0.f; accB[mt][nt][e] = 0.f; }

    // ---- W resident load: 2 proj x 256 rows x 16 chunks = 8192 chunks ----
    {
        #pragma unroll 4
        for (int i = 0; i < 32; i++) {
            int flat = tid + i * 256;
            int v = flat >> 12, rem = flat & 4095, k = rem >> 4, c = rem & 15;
            const __half* wp = v ? g_wb : g_wa;
            const char* src = (const char*)(wp + (size_t)k * SIZE + m0 + c * 8);
            CP_ASYNC16(sb + v * W_PROJ + k * WKPAD + c * 16, src);
        }
        CP_COMMIT();
    }

    // X register staging: thread owns k-row (tid>>3), 16 n-cols (tid&7)*16
    const int xk = tid >> 3;
    const int xc16 = (tid & 7) * 16;
    float r0v[16], r1v[16];

    auto ldg_x = [&](float (&r)[16], int n0, int kt) {
        const float* src = x + (size_t)(kt * BK + xk) * BATCH + n0 + xc16;
        #pragma unroll
        for (int i = 0; i < 4; i++) {
            float4 a = *(const float4*)(src + i * 4);
            r[i * 4] = a.x; r[i * 4 + 1] = a.y; r[i * 4 + 2] = a.z; r[i * 4 + 3] = a.w;
        }
    };
    auto sts_x = [&](float (&r)[16], int xstage) {
        unsigned short h[16];
        #pragma unroll
        for (int e = 0; e < 16; e++) {
            __half hb = __float2half_rn(r[e]);
            h[e] = *(unsigned short*)&hb;
        }
        char* hrow = smem + OFF_X + xstage * X_STAGE + xk * XBPAD + xc16 * 2;
        #pragma unroll
        for (int i = 0; i < 4; i++)
            *(ushort4*)(hrow + i * 8) = make_ushort4(h[4 * i], h[4 * i + 1], h[4 * i + 2], h[4 * i + 3]);
    };

    // ldmatrix per-lane address components
    const int g8 = lane >> 3;
    const int r8 = lane & 7;
    const uint32_t w_off = (uint32_t)(((g8 >> 1) * 8 + r8) * WKPAD + (g8 & 1) * 16 + warp_m * 64);
    const uint32_t x_off = (uint32_t)(((g8 & 1) * 8 + r8) * XBPAD + (g8 >> 1) * 16 + warp_n * 128);

    // prologue: X(0), X(1) loaded; X(0) STS'd; W landed.
    const int n0_first = nbase * BN;
    ldg_x(r0v, n0_first, 0);
    ldg_x(r1v, n0_first, 1);
    CP_WAIT0();
    sts_x(r0v, 0);

    auto body = [&](int q, float (&ld)[16], float (&st)[16]) {
        const int kt = q & 7;
        const int n0 = (nbase + (q >> 3) * HALF_CTAS) * BN;
        const uint32_t xbase = sb + OFF_X + (q & 1) * X_STAGE;
        const uint32_t wkbase = sb + (uint32_t)(kt * BK) * WKPAD + w_off;

        __syncthreads();     // publish X(q)

        const int q1 = q + 1;
        if (q1 < Q) sts_x(st, q1 & 1);
        const int q2 = q + 2;
        if (q2 < Q) ldg_x(ld, (nbase + (q2 >> 3) * HALF_CTAS) * BN, q2 & 7);

        #pragma unroll
        for (int ks = 0; ks < 2; ks++) {
            // X fragments: 8 n-tiles (shared across both projections and both mt)
            uint32_t xf[8][2];
            #pragma unroll
            for (int j = 0; j < 4; j++) {
                const uint32_t xo = xbase + x_off + ks * 16 * XBPAD + j * 32;
                uint32_t a0, a1, a2, a3;
                LDSM_X4_T(a0, a1, a2, a3, xo);
                xf[2 * j][0] = a0; xf[2 * j][1] = a1;
                xf[2 * j + 1][0] = a2; xf[2 * j + 1][1] = a3;
            }
            // W fragments: 2 proj x 2 mt from resident smem
            uint32_t fa[2][4], fb[2][4];
            #pragma unroll
            for (int mt = 0; mt < 2; mt++) {
                const uint32_t ao = wkbase + ks * 16 * WKPAD + mt * 32;
                LDSM_X4_T(fa[mt][0], fa[mt][1], fa[mt][2], fa[mt][3], ao);
                LDSM_X4_T(fb[mt][0], fb[mt][1], fb[mt][2], fb[mt][3], ao + W_PROJ);
            }
            #pragma unroll
            for (int mt = 0; mt < 2; mt++) {
                #pragma unroll
                for (int nt = 0; nt < 8; nt++) MMA_F16(accA[mt][nt], fa[mt], xf[nt]);
                #pragma unroll
                for (int nt = 0; nt < 8; nt++) MMA_F16(accB[mt][nt], fb[mt], xf[nt]);
            }
        }

        if (kt == 7) {
            const int row_in = lane >> 2;
            const int col2 = (lane & 3) * 2;
            #pragma unroll
            for (int mt = 0; mt < 2; mt++) {
                const int j1 = m0 + warp_m * 32 + mt * 16 + row_in;
                const int j2 = j1 + 8;
                const float c0a = g_c0[j1], cAa = g_cA[j1], cBa = g_cB[j1], cXa = g_cAB[j1];
                const float c0b = g_c0[j2], cAb = g_cA[j2], cBb = g_cB[j2], cXb = g_cAB[j2];
                #pragma unroll
                for (int nt = 0; nt < 8; nt++) {
                    const int n = n0 + warp_n * 64 + nt * 8 + col2;
                    float2 o1, o2;
                    {
                        float A = accA[mt][nt][0], B = accB[mt][nt][0];
                        o1.x = fmaf(cXa * A, B, fmaf(cAa, A, fmaf(cBa, B, c0a)));
                        A = accA[mt][nt][1]; B = accB[mt][nt][1];
                        o1.y = fmaf(cXa * A, B, fmaf(cAa, A, fmaf(cBa, B, c0a)));
                    }
                    {
                        float A = accA[mt][nt][2], B = accB[mt][nt][2];
                        o2.x = fmaf(cXb * A, B, fmaf(cAb, A, fmaf(cBb, B, c0b)));
                        A = accA[mt][nt][3]; B = accB[mt][nt][3];
                        o2.y = fmaf(cXb * A, B, fmaf(cAb, A, fmaf(cBb, B, c0b)));
                    }
                    *(float2*)&out[(size_t)j1 * BATCH + n] = o1;
                    *(float2*)&out[(size_t)j2 * BATCH + n] = o2;
                    #pragma unroll
                    for (int e = 0; e < 4; e++) { accA[mt][nt][e] = 0.f; accB[mt][nt][e] = 0.f; }
                }
            }
        }
    };

    #pragma unroll 1
    for (int q = 0; q < Q; q += 2) {
        body(q,     r0v, r1v);   // LDG(q+2)->r0, STS X(q+1) from r1
        body(q + 1, r1v, r0v);   // LDG(q+3)->r1, STS X(q+2) from r0
    }
}

// ---------------- launch ----------------
extern "C" void kernel_launch(void* const* d_in, const int* in_sizes, int n_in,
                              void* d_out, int out_size) {
    const float* x  = (const float*)d_in[0];   // [PREV,  BATCH]
    const float* wa = (const float*)d_in[1];   // [SIZE,  PREV]
    const float* wb = (const float*)d_in[2];   // [SIZE,  PREV]
    const float* wt = (const float*)d_in[3];   // [16,    SIZE]
    float* out = (float*)d_out;                // [SIZE,  BATCH]

    cudaFuncSetAttribute(fused_logic_mma_kernel,
                         cudaFuncAttributeMaxDynamicSharedMemorySize, SMEM_TOTAL);

    prep_kernel<<<128, 128>>>(wa, wb, wt);
    fused_logic_mma_kernel<<<NCTA, 256, SMEM_TOTAL>>>(x, out);
}

// round 10
// speedup vs baseline: 4.9369x; 1.0338x over previous
#include <cuda_runtime.h>
#include <cuda_fp16.h>
#include <cstdint>

#define SIZE  256
#define PREV  256
#define BATCH 32768

#define BM 128
#define BN 128
#define BK 32
#define NUM_KTILES (PREV / BK)       // 8
#define N_NTILES (BATCH / BN)        // 256
#define NCTA 148
#define HALF_CTAS (NCTA / 2)         // 74
#define NTHREADS 512

// ---------------- scratch ----------------
__device__ __align__(128) __half g_wa[PREV * SIZE];   // k-major [k][m]
__device__ __align__(128) __half g_wb[PREV * SIZE];
__device__ float g_c0[SIZE];
__device__ float g_cA[SIZE];
__device__ float g_cB[SIZE];
__device__ float g_cAB[SIZE];

// ---------------- smem layout ----------------
#define WKPAD 272
#define XBPAD 272
#define W_PROJ 69632                        // 256 k-rows x 272
#define OFF_X  (2 * W_PROJ)                 // 139264
#define X_STAGE 8704                        // 32 k-rows x 272
#define SMEM_TOTAL (OFF_X + 2 * X_STAGE)    // 156672

// ============================ PTX helpers ============================
__device__ __forceinline__ uint32_t smem_u32(const void* p) {
    uint32_t a;
    asm("{ .reg .u64 t; cvta.to.shared.u64 t, %1; cvt.u32.u64 %0, t; }" : "=r"(a) : "l"(p));
    return a;
}
#define CP_ASYNC16(dst, src) \
    asm volatile("cp.async.cg.shared.global [%0], [%1], 16;" :: "r"(dst), "l"(src))
#define CP_COMMIT() asm volatile("cp.async.commit_group;" ::: "memory")
#define CP_WAIT0()  asm volatile("cp.async.wait_group 0;" ::: "memory")

#define LDSM_X4_T(r0, r1, r2, r3, addr)                                         \
    asm volatile("ldmatrix.sync.aligned.m8n8.x4.trans.shared.b16 {%0,%1,%2,%3}, [%4];" \
                 : "=r"(r0), "=r"(r1), "=r"(r2), "=r"(r3) : "r"(addr))

#define MMA_F16(c, a, b)                                                        \
    asm volatile("mma.sync.aligned.m16n8k16.row.col.f32.f16.f16.f32 "           \
                 "{%0,%1,%2,%3}, {%4,%5,%6,%7}, {%8,%9}, {%0,%1,%2,%3};"        \
                 : "+f"((c)[0]), "+f"((c)[1]), "+f"((c)[2]), "+f"((c)[3])       \
                 : "r"((a)[0]), "r"((a)[1]), "r"((a)[2]), "r"((a)[3]),          \
                   "r"((b)[0]), "r"((b)[1]))

// ---------------- prep: softmax rows -> transposed fp16 (+ coefs) ----------------
__global__ void prep_kernel(const float* __restrict__ wa, const float* __restrict__ wb,
                            const float* __restrict__ wt) {
    __shared__ unsigned short sh[PREV * 4];
    const int bx = blockIdx.x;
    const float* src = (bx < 64) ? wa : wb;
    __half* dst = (bx < 64) ? g_wa : g_wb;
    const int m0 = (bx & 63) * 4;
    const int wid = threadIdx.x >> 5;
    const int lane = threadIdx.x & 31;

    const float* row = src + (size_t)(m0 + wid) * PREV;
    float v[8];
    float mx = -1e30f;
    #pragma unroll
    for (int i = 0; i < 8; i++) { v[i] = row[lane + 32 * i]; mx = fmaxf(mx, v[i]); }
    #pragma unroll
    for (int o = 16; o; o >>= 1) mx = fmaxf(mx, __shfl_xor_sync(0xffffffffu, mx, o));
    float e[8], s = 0.f;
    #pragma unroll
    for (int i = 0; i < 8; i++) { e[i] = expf(v[i] - mx); s += e[i]; }
    #pragma unroll
    for (int o = 16; o; o >>= 1) s += __shfl_xor_sync(0xffffffffu, s, o);
    const float inv = 1.0f / s;
    #pragma unroll
    for (int i = 0; i < 8; i++) {
        __half h = __float2half_rn(e[i] * inv);
        sh[(lane + 32 * i) * 4 + wid] = *(unsigned short*)&h;
    }

    if (bx < 2) {
        const int j = bx * 128 + threadIdx.x;
        float p[16];
        float m = -1e30f;
        #pragma unroll
        for (int g = 0; g < 16; g++) { p[g] = wt[g * SIZE + j]; m = fmaxf(m, p[g]); }
        float ss = 0.f;
        #pragma unroll
        for (int g = 0; g < 16; g++) { p[g] = expf(p[g] - m); ss += p[g]; }
        const float iv = 1.0f / ss;
        #pragma unroll
        for (int g = 0; g < 16; g++) p[g] *= iv;
        g_c0[j]  = p[8] + p[9] + p[10] + p[11] + p[12] + p[13] + p[14] + p[15];
        g_cA[j]  = p[2] + p[3] + p[6] + p[7] - p[8] - p[9] - p[12] - p[13];
        g_cB[j]  = p[4] + p[5] + p[6] + p[7] - p[8] - p[9] - p[10] - p[11];
        g_cAB[j] = p[1] - p[2] - p[4] - 2.f * p[6] - p[7]
                 + p[8] + 2.f * p[9] + p[11] + p[13] - p[14];
    }

    __syncthreads();
    const int t = threadIdx.x;
    *(ushort4*)&dst[(size_t)t * SIZE + m0]         = *(ushort4*)&sh[t * 4];
    *(ushort4*)&dst[(size_t)(t + 128) * SIZE + m0] = *(ushort4*)&sh[(t + 128) * 4];
}

// ---------------- main kernel: W-resident, 512 threads (16 warps, 4/SMSP) ----------------
// CTA pinned to m-half (bid&1). 16 warps as 4(m) x 4(n); warp tile 32m x 32n.
__global__ void __launch_bounds__(NTHREADS, 1)
fused_logic_mma_kernel(const float* __restrict__ x, float* __restrict__ out) {
    extern __shared__ char smem[];
    const uint32_t sb = smem_u32(smem);
    const int tid = threadIdx.x;
    const int wid = tid >> 5;
    const int lane = tid & 31;
    const int warp_m = wid >> 2;      // 0..3
    const int warp_n = wid & 3;       // 0..3
    const int bid = blockIdx.x;
    const int m0 = (bid & 1) * BM;
    const int nbase = bid >> 1;       // 0..73

    const int ntiles = (N_NTILES - 1 - nbase) / HALF_CTAS + 1;   // 3 or 4
    const int Q = ntiles * NUM_KTILES;

    float accA[2][4][4];
    float accB[2][4][4];
    #pragma unroll
    for (int mt = 0; mt < 2; mt++)
        #pragma unroll
        for (int nt = 0; nt < 4; nt++)
            #pragma unroll
            for (int e = 0; e < 4; e++) { accA[mt][nt][e] = 0.f; accB[mt][nt][e] = 0.f; }

    // ---- W resident load: 8192 chunks over 512 threads ----
    {
        #pragma unroll 4
        for (int i = 0; i < 16; i++) {
            int flat = tid + i * NTHREADS;
            int v = flat >> 12, rem = flat & 4095, k = rem >> 4, c = rem & 15;
            const __half* wp = v ? g_wb : g_wa;
            const char* src = (const char*)(wp + (size_t)k * SIZE + m0 + c * 8);
            CP_ASYNC16(sb + v * W_PROJ + k * WKPAD + c * 16, src);
        }
        CP_COMMIT();
    }

    // X register staging: thread owns k-row (tid>>4), 8 n-cols (tid&15)*8
    const int xk = tid >> 4;
    const int xc8 = (tid & 15) * 8;
    float r0v[8], r1v[8];

    auto ldg_x = [&](float (&r)[8], int n0, int kt) {
        const float* src = x + (size_t)(kt * BK + xk) * BATCH + n0 + xc8;
        float4 a = *(const float4*)src;
        float4 b = *(const float4*)(src + 4);
        r[0] = a.x; r[1] = a.y; r[2] = a.z; r[3] = a.w;
        r[4] = b.x; r[5] = b.y; r[6] = b.z; r[7] = b.w;
    };
    auto sts_x = [&](float (&r)[8], int xstage) {
        unsigned short h[8];
        #pragma unroll
        for (int e = 0; e < 8; e++) {
            __half hb = __float2half_rn(r[e]);
            h[e] = *(unsigned short*)&hb;
        }
        char* hrow = smem + OFF_X + xstage * X_STAGE + xk * XBPAD + xc8 * 2;
        *(ushort4*)hrow       = make_ushort4(h[0], h[1], h[2], h[3]);
        *(ushort4*)(hrow + 8) = make_ushort4(h[4], h[5], h[6], h[7]);
    };

    // ldmatrix per-lane address components
    const int g8 = lane >> 3;
    const int r8 = lane & 7;
    const uint32_t w_off = (uint32_t)(((g8 >> 1) * 8 + r8) * WKPAD + (g8 & 1) * 16 + warp_m * 64);
    const uint32_t x_off = (uint32_t)(((g8 & 1) * 8 + r8) * XBPAD + (g8 >> 1) * 16 + warp_n * 64);

    // prologue
    const int n0_first = nbase * BN;
    ldg_x(r0v, n0_first, 0);
    ldg_x(r1v, n0_first, 1);
    CP_WAIT0();                       // W resident
    sts_x(r0v, 0);

    auto body = [&](int q, float (&ld)[8], float (&st)[8]) {
        const int kt = q & 7;
        const int n0 = (nbase + (q >> 3) * HALF_CTAS) * BN;
        const uint32_t xbase = sb + OFF_X + (q & 1) * X_STAGE;
        const uint32_t wkbase = sb + (uint32_t)(kt * BK) * WKPAD + w_off;

        __syncthreads();     // publish X(q)

        const int q1 = q + 1;
        if (q1 < Q) sts_x(st, q1 & 1);
        const int q2 = q + 2;
        if (q2 < Q) ldg_x(ld, (nbase + (q2 >> 3) * HALF_CTAS) * BN, q2 & 7);

        #pragma unroll
        for (int ks = 0; ks < 2; ks++) {
            // X fragments: 4 n-tiles
            uint32_t xf[4][2];
            #pragma unroll
            for (int j = 0; j < 2; j++) {
                const uint32_t xo = xbase + x_off + ks * 16 * XBPAD + j * 32;
                uint32_t a0, a1, a2, a3;
                LDSM_X4_T(a0, a1, a2, a3, xo);
                xf[2 * j][0] = a0; xf[2 * j][1] = a1;
                xf[2 * j + 1][0] = a2; xf[2 * j + 1][1] = a3;
            }
            // W fragments: 2 proj x 2 mt from resident smem
            uint32_t fa[2][4], fb[2][4];
            #pragma unroll
            for (int mt = 0; mt < 2; mt++) {
                const uint32_t ao = wkbase + ks * 16 * WKPAD + mt * 32;
                LDSM_X4_T(fa[mt][0], fa[mt][1], fa[mt][2], fa[mt][3], ao);
                LDSM_X4_T(fb[mt][0], fb[mt][1], fb[mt][2], fb[mt][3], ao + W_PROJ);
            }
            #pragma unroll
            for (int mt = 0; mt < 2; mt++) {
                #pragma unroll
                for (int nt = 0; nt < 4; nt++) MMA_F16(accA[mt][nt], fa[mt], xf[nt]);
                #pragma unroll
                for (int nt = 0; nt < 4; nt++) MMA_F16(accB[mt][nt], fb[mt], xf[nt]);
            }
        }

        if (kt == 7) {
            const int row_in = lane >> 2;
            const int col2 = (lane & 3) * 2;
            #pragma unroll
            for (int mt = 0; mt < 2; mt++) {
                const int j1 = m0 + warp_m * 32 + mt * 16 + row_in;
                const int j2 = j1 + 8;
                const float c0a = g_c0[j1], cAa = g_cA[j1], cBa = g_cB[j1], cXa = g_cAB[j1];
                const float c0b = g_c0[j2], cAb = g_cA[j2], cBb = g_cB[j2], cXb = g_cAB[j2];
                #pragma unroll
                for (int nt = 0; nt < 4; nt++) {
                    const int n = n0 + warp_n * 32 + nt * 8 + col2;
                    float2 o1, o2;
                    {
                        float A = accA[mt][nt][0], B = accB[mt][nt][0];
                        o1.x = fmaf(cXa * A, B, fmaf(cAa, A, fmaf(cBa, B, c0a)));
                        A = accA[mt][nt][1]; B = accB[mt][nt][1];
                        o1.y = fmaf(cXa * A, B, fmaf(cAa, A, fmaf(cBa, B, c0a)));
                    }
                    {
                        float A = accA[mt][nt][2], B = accB[mt][nt][2];
                        o2.x = fmaf(cXb * A, B, fmaf(cAb, A, fmaf(cBb, B, c0b)));
                        A = accA[mt][nt][3]; B = accB[mt][nt][3];
                        o2.y = fmaf(cXb * A, B, fmaf(cAb, A, fmaf(cBb, B, c0b)));
                    }
                    *(float2*)&out[(size_t)j1 * BATCH + n] = o1;
                    *(float2*)&out[(size_t)j2 * BATCH + n] = o2;
                    #pragma unroll
                    for (int e = 0; e < 4; e++) { accA[mt][nt][e] = 0.f; accB[mt][nt][e] = 0.f; }
                }
            }
        }
    };

    #pragma unroll 1
    for (int q = 0; q < Q; q += 2) {
        body(q,     r0v, r1v);   // LDG(q+2)->r0, STS X(q+1) from r1
        body(q + 1, r1v, r0v);   // LDG(q+3)->r1, STS X(q+2) from r0
    }
}

// ---------------- launch ----------------
extern "C" void kernel_launch(void* const* d_in, const int* in_sizes, int n_in,
                              void* d_out, int out_size) {
    const float* x  = (const float*)d_in[0];   // [PREV,  BATCH]
    const float* wa = (const float*)d_in[1];   // [SIZE,  PREV]
    const float* wb = (const float*)d_in[2];   // [SIZE,  PREV]
    const float* wt = (const float*)d_in[3];   // [16,    SIZE]
    float* out = (float*)d_out;                // [SIZE,  BATCH]

    cudaFuncSetAttribute(fused_logic_mma_kernel,
                         cudaFuncAttributeMaxDynamicSharedMemorySize, SMEM_TOTAL);

    prep_kernel<<<128, 128>>>(wa, wb, wt);
    fused_logic_mma_kernel<<<NCTA, NTHREADS, SMEM_TOTAL>>>(x, out);
}

// round 11
// speedup vs baseline: 5.0480x; 1.0225x over previous
#include <cuda_runtime.h>
#include <cuda_fp16.h>
#include <cstdint>

#define SIZE  256
#define PREV  256
#define BATCH 32768

#define BM 128
#define BN 128
#define BK 32
#define NUM_KTILES (PREV / BK)       // 8
#define N_NTILES (BATCH / BN)        // 256
#define NCTA 148
#define HALF_CTAS (NCTA / 2)         // 74
#define NTHREADS 512

// ---------------- scratch ----------------
__device__ __align__(128) __half g_wa[PREV * SIZE];   // k-major [k][m]
__device__ __align__(128) __half g_wb[PREV * SIZE];
__device__ float g_c0[SIZE];
__device__ float g_cA[SIZE];
__device__ float g_cB[SIZE];
__device__ float g_cAB[SIZE];

// ---------------- smem layout ----------------
#define WKPAD 272
#define XBPAD 272
#define W_PROJ 69632                        // 256 k-rows x 272
#define OFF_X  (2 * W_PROJ)                 // 139264
#define X_STAGE 8704                        // 32 k-rows x 272
#define SMEM_TOTAL (OFF_X + 4 * X_STAGE)    // 174080

// ============================ PTX helpers ============================
__device__ __forceinline__ uint32_t smem_u32(const void* p) {
    uint32_t a;
    asm("{ .reg .u64 t; cvta.to.shared.u64 t, %1; cvt.u32.u64 %0, t; }" : "=r"(a) : "l"(p));
    return a;
}
#define CP_ASYNC16(dst, src) \
    asm volatile("cp.async.cg.shared.global [%0], [%1], 16;" :: "r"(dst), "l"(src))
#define CP_COMMIT() asm volatile("cp.async.commit_group;" ::: "memory")
#define CP_WAIT0()  asm volatile("cp.async.wait_group 0;" ::: "memory")

#define LDSM_X4_T(r0, r1, r2, r3, addr)                                         \
    asm volatile("ldmatrix.sync.aligned.m8n8.x4.trans.shared.b16 {%0,%1,%2,%3}, [%4];" \
                 : "=r"(r0), "=r"(r1), "=r"(r2), "=r"(r3) : "r"(addr))

#define MMA_F16(c, a, b)                                                        \
    asm volatile("mma.sync.aligned.m16n8k16.row.col.f32.f16.f16.f32 "           \
                 "{%0,%1,%2,%3}, {%4,%5,%6,%7}, {%8,%9}, {%0,%1,%2,%3};"        \
                 : "+f"((c)[0]), "+f"((c)[1]), "+f"((c)[2]), "+f"((c)[3])       \
                 : "r"((a)[0]), "r"((a)[1]), "r"((a)[2]), "r"((a)[3]),          \
                   "r"((b)[0]), "r"((b)[1]))

// ---------------- prep: softmax rows -> transposed fp16 (+ coefs) ----------------
__global__ void prep_kernel(const float* __restrict__ wa, const float* __restrict__ wb,
                            const float* __restrict__ wt) {
    __shared__ unsigned short sh[PREV * 4];
    const int bx = blockIdx.x;
    const float* src = (bx < 64) ? wa : wb;
    __half* dst = (bx < 64) ? g_wa : g_wb;
    const int m0 = (bx & 63) * 4;
    const int wid = threadIdx.x >> 5;
    const int lane = threadIdx.x & 31;

    const float* row = src + (size_t)(m0 + wid) * PREV;
    float v[8];
    float mx = -1e30f;
    #pragma unroll
    for (int i = 0; i < 8; i++) { v[i] = row[lane + 32 * i]; mx = fmaxf(mx, v[i]); }
    #pragma unroll
    for (int o = 16; o; o >>= 1) mx = fmaxf(mx, __shfl_xor_sync(0xffffffffu, mx, o));
    float e[8], s = 0.f;
    #pragma unroll
    for (int i = 0; i < 8; i++) { e[i] = expf(v[i] - mx); s += e[i]; }
    #pragma unroll
    for (int o = 16; o; o >>= 1) s += __shfl_xor_sync(0xffffffffu, s, o);
    const float inv = 1.0f / s;
    #pragma unroll
    for (int i = 0; i < 8; i++) {
        __half h = __float2half_rn(e[i] * inv);
        sh[(lane + 32 * i) * 4 + wid] = *(unsigned short*)&h;
    }

    if (bx < 2) {
        const int j = bx * 128 + threadIdx.x;
        float p[16];
        float m = -1e30f;
        #pragma unroll
        for (int g = 0; g < 16; g++) { p[g] = wt[g * SIZE + j]; m = fmaxf(m, p[g]); }
        float ss = 0.f;
        #pragma unroll
        for (int g = 0; g < 16; g++) { p[g] = expf(p[g] - m); ss += p[g]; }
        const float iv = 1.0f / ss;
        #pragma unroll
        for (int g = 0; g < 16; g++) p[g] *= iv;
        g_c0[j]  = p[8] + p[9] + p[10] + p[11] + p[12] + p[13] + p[14] + p[15];
        g_cA[j]  = p[2] + p[3] + p[6] + p[7] - p[8] - p[9] - p[12] - p[13];
        g_cB[j]  = p[4] + p[5] + p[6] + p[7] - p[8] - p[9] - p[10] - p[11];
        g_cAB[j] = p[1] - p[2] - p[4] - 2.f * p[6] - p[7]
                 + p[8] + 2.f * p[9] + p[11] + p[13] - p[14];
    }

    __syncthreads();
    const int t = threadIdx.x;
    *(ushort4*)&dst[(size_t)t * SIZE + m0]         = *(ushort4*)&sh[t * 4];
    *(ushort4*)&dst[(size_t)(t + 128) * SIZE + m0] = *(ushort4*)&sh[(t + 128) * 4];
}

// ---------------- main kernel: W-resident, 4-stage X ring, barrier per 2 steps ----------------
__global__ void __launch_bounds__(NTHREADS, 1)
fused_logic_mma_kernel(const float* __restrict__ x, float* __restrict__ out) {
    extern __shared__ char smem[];
    const uint32_t sb = smem_u32(smem);
    const int tid = threadIdx.x;
    const int wid = tid >> 5;
    const int lane = tid & 31;
    const int warp_m = wid >> 2;      // 0..3
    const int warp_n = wid & 3;       // 0..3
    const int bid = blockIdx.x;
    const int m0 = (bid & 1) * BM;
    const int nbase = bid >> 1;       // 0..73

    const int ntiles = (N_NTILES - 1 - nbase) / HALF_CTAS + 1;   // 3 or 4
    const int Q = ntiles * NUM_KTILES;                           // 24 or 32 (even)

    float accA[2][4][4];
    float accB[2][4][4];
    #pragma unroll
    for (int mt = 0; mt < 2; mt++)
        #pragma unroll
        for (int nt = 0; nt < 4; nt++)
            #pragma unroll
            for (int e = 0; e < 4; e++) { accA[mt][nt][e] = 0.f; accB[mt][nt][e] = 0.f; }

    // ---- W resident load ----
    {
        #pragma unroll 4
        for (int i = 0; i < 16; i++) {
            int flat = tid + i * NTHREADS;
            int v = flat >> 12, rem = flat & 4095, k = rem >> 4, c = rem & 15;
            const __half* wp = v ? g_wb : g_wa;
            const char* src = (const char*)(wp + (size_t)k * SIZE + m0 + c * 8);
            CP_ASYNC16(sb + v * W_PROJ + k * WKPAD + c * 16, src);
        }
        CP_COMMIT();
    }

    // X register staging
    const int xk = tid >> 4;
    const int xc8 = (tid & 15) * 8;
    float r0v[8], r1v[8];

    auto ldg_x = [&](float (&r)[8], int q) {
        const int n0 = (nbase + (q >> 3) * HALF_CTAS) * BN;
        const float* src = x + (size_t)((q & 7) * BK + xk) * BATCH + n0 + xc8;
        float4 a = *(const float4*)src;
        float4 b = *(const float4*)(src + 4);
        r[0] = a.x; r[1] = a.y; r[2] = a.z; r[3] = a.w;
        r[4] = b.x; r[5] = b.y; r[6] = b.z; r[7] = b.w;
    };
    auto sts_x = [&](float (&r)[8], int q) {
        unsigned short h[8];
        #pragma unroll
        for (int e = 0; e < 8; e++) {
            __half hb = __float2half_rn(r[e]);
            h[e] = *(unsigned short*)&hb;
        }
        char* hrow = smem + OFF_X + (q & 3) * X_STAGE + xk * XBPAD + xc8 * 2;
        *(ushort4*)hrow       = make_ushort4(h[0], h[1], h[2], h[3]);
        *(ushort4*)(hrow + 8) = make_ushort4(h[4], h[5], h[6], h[7]);
    };

    // ldmatrix per-lane address components
    const int g8 = lane >> 3;
    const int r8 = lane & 7;
    const uint32_t w_off = (uint32_t)(((g8 >> 1) * 8 + r8) * WKPAD + (g8 & 1) * 16 + warp_m * 64);
    const uint32_t x_off = (uint32_t)(((g8 & 1) * 8 + r8) * XBPAD + (g8 >> 1) * 16 + warp_n * 64);

    // prologue: stages 0,1 filled and published; regs hold X(2),X(3)
    ldg_x(r0v, 0);
    ldg_x(r1v, 1);
    CP_WAIT0();                       // W resident
    sts_x(r0v, 0);
    sts_x(r1v, 1);
    ldg_x(r0v, 2);
    ldg_x(r1v, 3);
    __syncthreads();

    auto body = [&](int q, float (&reg)[8]) {
        const int kt = q & 7;
        const int n0 = (nbase + (q >> 3) * HALF_CTAS) * BN;
        const uint32_t xbase = sb + OFF_X + (q & 3) * X_STAGE;
        const uint32_t wkbase = sb + (uint32_t)(kt * BK) * WKPAD + w_off;

        // stage X(q+2) now (published by the pair barrier, 1-2 steps away)
        if (q + 2 < Q) sts_x(reg, q + 2);
        if (q + 4 < Q) ldg_x(reg, q + 4);

        #pragma unroll
        for (int ks = 0; ks < 2; ks++) {
            uint32_t xf[4][2];
            #pragma unroll
            for (int j = 0; j < 2; j++) {
                const uint32_t xo = xbase + x_off + ks * 16 * XBPAD + j * 32;
                uint32_t a0, a1, a2, a3;
                LDSM_X4_T(a0, a1, a2, a3, xo);
                xf[2 * j][0] = a0; xf[2 * j][1] = a1;
                xf[2 * j + 1][0] = a2; xf[2 * j + 1][1] = a3;
            }
            uint32_t fa[2][4], fb[2][4];
            #pragma unroll
            for (int mt = 0; mt < 2; mt++) {
                const uint32_t ao = wkbase + ks * 16 * WKPAD + mt * 32;
                LDSM_X4_T(fa[mt][0], fa[mt][1], fa[mt][2], fa[mt][3], ao);
                LDSM_X4_T(fb[mt][0], fb[mt][1], fb[mt][2], fb[mt][3], ao + W_PROJ);
            }
            #pragma unroll
            for (int mt = 0; mt < 2; mt++) {
                #pragma unroll
                for (int nt = 0; nt < 4; nt++) MMA_F16(accA[mt][nt], fa[mt], xf[nt]);
                #pragma unroll
                for (int nt = 0; nt < 4; nt++) MMA_F16(accB[mt][nt], fb[mt], xf[nt]);
            }
        }

        if (kt == 7) {
            const int row_in = lane >> 2;
            const int col2 = (lane & 3) * 2;
            #pragma unroll
            for (int mt = 0; mt < 2; mt++) {
                const int j1 = m0 + warp_m * 32 + mt * 16 + row_in;
                const int j2 = j1 + 8;
                const float c0a = g_c0[j1], cAa = g_cA[j1], cBa = g_cB[j1], cXa = g_cAB[j1];
                const float c0b = g_c0[j2], cAb = g_cA[j2], cBb = g_cB[j2], cXb = g_cAB[j2];
                #pragma unroll
                for (int nt = 0; nt < 4; nt++) {
                    const int n = n0 + warp_n * 32 + nt * 8 + col2;
                    float2 o1, o2;
                    {
                        float A = accA[mt][nt][0], B = accB[mt][nt][0];
                        o1.x = fmaf(cXa * A, B, fmaf(cAa, A, fmaf(cBa, B, c0a)));
                        A = accA[mt][nt][1]; B = accB[mt][nt][1];
                        o1.y = fmaf(cXa * A, B, fmaf(cAa, A, fmaf(cBa, B, c0a)));
                    }
                    {
                        float A = accA[mt][nt][2], B = accB[mt][nt][2];
                        o2.x = fmaf(cXb * A, B, fmaf(cAb, A, fmaf(cBb, B, c0b)));
                        A = accA[mt][nt][3]; B = accB[mt][nt][3];
                        o2.y = fmaf(cXb * A, B, fmaf(cAb, A, fmaf(cBb, B, c0b)));
                    }
                    *(float2*)&out[(size_t)j1 * BATCH + n] = o1;
                    *(float2*)&out[(size_t)j2 * BATCH + n] = o2;
                    #pragma unroll
                    for (int e = 0; e < 4; e++) { accA[mt][nt][e] = 0.f; accB[mt][nt][e] = 0.f; }
                }
            }
        }
    };

    #pragma unroll 1
    for (int q = 0; q < Q; q += 2) {
        body(q,     r0v);     // STS X(q+2) from r0, LDG X(q+4)->r0
        body(q + 1, r1v);     // STS X(q+3) from r1, LDG X(q+5)->r1
        __syncthreads();      // publish stages (q+2),(q+3); fence reuse
    }
}

// ---------------- launch ----------------
extern "C" void kernel_launch(void* const* d_in, const int* in_sizes, int n_in,
                              void* d_out, int out_size) {
    const float* x  = (const float*)d_in[0];   // [PREV,  BATCH]
    const float* wa = (const float*)d_in[1];   // [SIZE,  PREV]
    const float* wb = (const float*)d_in[2];   // [SIZE,  PREV]
    const float* wt = (const float*)d_in[3];   // [16,    SIZE]
    float* out = (float*)d_out;                // [SIZE,  BATCH]

    cudaFuncSetAttribute(fused_logic_mma_kernel,
                         cudaFuncAttributeMaxDynamicSharedMemorySize, SMEM_TOTAL);

    prep_kernel<<<128, 128>>>(wa, wb, wt);
    fused_logic_mma_kernel<<<NCTA, NTHREADS, SMEM_TOTAL>>>(x, out);
}